// round 1
// baseline (speedup 1.0000x reference)
#include <cuda_runtime.h>
#include <cuda_bf16.h>
#include <cstdint>

// Problem constants
#define N_TOK   4096
#define D_MODEL 768
#define N_HEADS 12
#define D_K     64

// ---------------------------------------------------------------------------
// Scratch (no cudaMalloc allowed): q,k,v in [H][n][dk] layout, attn out [n][d]
// ---------------------------------------------------------------------------
__device__ float g_q[N_HEADS * N_TOK * D_K];
__device__ float g_k[N_HEADS * N_TOK * D_K];
__device__ float g_v[N_HEADS * N_TOK * D_K];
__device__ float g_attn[N_TOK * D_MODEL];

// ---------------------------------------------------------------------------
// GEMM: C[m, o] = sum_k X[m,k] * W[o,k] + bias[o]
// X: [M, K] row-major, W: [N, K] row-major (torch Linear weight)
// SCATTER: write C to [h][m][t] with h = o/64, t = o%64 (head split)
// BM=BN=128, BK=16, 256 threads, 8x8 per thread
// ---------------------------------------------------------------------------
#define BM 128
#define BN 128
#define BK 16
#define TM 8
#define TN 8

template <bool SCATTER>
__global__ void __launch_bounds__(256) gemm_bias_kernel(
    const float* __restrict__ X, const float* __restrict__ W,
    const float* __restrict__ bias, float* __restrict__ out,
    int M, int N, int K)
{
    __shared__ float As[BK][BM];
    __shared__ float Bs[BK][BN];

    const int tid = threadIdx.x;
    const int tx = tid & 15;         // 0..15 -> N direction
    const int ty = tid >> 4;         // 0..15 -> M direction
    const int m0 = blockIdx.y * BM;
    const int n0 = blockIdx.x * BN;

    const float* Xp = X + (size_t)m0 * K;
    const float* Wp = W + (size_t)n0 * K;

    float c[TM][TN];
#pragma unroll
    for (int i = 0; i < TM; i++)
#pragma unroll
        for (int j = 0; j < TN; j++) c[i][j] = 0.0f;

    for (int k0 = 0; k0 < K; k0 += BK) {
        // Load A tile (128 rows x 16 k) as 512 float4, 2 per thread, transpose.
#pragma unroll
        for (int i = 0; i < 2; i++) {
            int v = tid + i * 256;
            int row = v >> 2;            // 4 float4 per row
            int kc4 = v & 3;
            float4 t = *(const float4*)(Xp + (size_t)row * K + k0 + kc4 * 4);
            As[kc4 * 4 + 0][row] = t.x;
            As[kc4 * 4 + 1][row] = t.y;
            As[kc4 * 4 + 2][row] = t.z;
            As[kc4 * 4 + 3][row] = t.w;
        }
        // Load W tile (128 out-rows x 16 k), transpose.
#pragma unroll
        for (int i = 0; i < 2; i++) {
            int v = tid + i * 256;
            int row = v >> 2;
            int kc4 = v & 3;
            float4 t = *(const float4*)(Wp + (size_t)row * K + k0 + kc4 * 4);
            Bs[kc4 * 4 + 0][row] = t.x;
            Bs[kc4 * 4 + 1][row] = t.y;
            Bs[kc4 * 4 + 2][row] = t.z;
            Bs[kc4 * 4 + 3][row] = t.w;
        }
        __syncthreads();

#pragma unroll
        for (int kk = 0; kk < BK; kk++) {
            float a[TM], b[TN];
            // vectorized smem reads
            float4 a0 = *(const float4*)&As[kk][ty * TM + 0];
            float4 a1 = *(const float4*)&As[kk][ty * TM + 4];
            float4 b0 = *(const float4*)&Bs[kk][tx * TN + 0];
            float4 b1 = *(const float4*)&Bs[kk][tx * TN + 4];
            a[0] = a0.x; a[1] = a0.y; a[2] = a0.z; a[3] = a0.w;
            a[4] = a1.x; a[5] = a1.y; a[6] = a1.z; a[7] = a1.w;
            b[0] = b0.x; b[1] = b0.y; b[2] = b0.z; b[3] = b0.w;
            b[4] = b1.x; b[5] = b1.y; b[6] = b1.z; b[7] = b1.w;
#pragma unroll
            for (int i = 0; i < TM; i++)
#pragma unroll
                for (int j = 0; j < TN; j++)
                    c[i][j] += a[i] * b[j];
        }
        __syncthreads();
    }

    // Epilogue: bias + store
    float bj[TN];
#pragma unroll
    for (int j = 0; j < TN; j++) bj[j] = bias[n0 + tx * TN + j];

#pragma unroll
    for (int i = 0; i < TM; i++) {
        int row = m0 + ty * TM + i;
#pragma unroll
        for (int j = 0; j < TN; j++) {
            int o = n0 + tx * TN + j;
            float val = c[i][j] + bj[j];
            if (SCATTER) {
                int h = o >> 6;
                int t = o & 63;
                out[((size_t)h * M + row) * D_K + t] = val;
            } else {
                out[(size_t)row * N + o] = val;
            }
        }
    }
}

// ---------------------------------------------------------------------------
// Flash attention, fp32.
// Grid: (n/64, H). Block: 256 threads (ty 0..15 rows, tx 0..15 cols).
// Each block: 64 query rows x full dk=64, streaming key tiles of 32.
// Per thread: S tile 4 rows x 2 cols; O tile 4 rows x 4 dk-cols.
// ---------------------------------------------------------------------------
__global__ void __launch_bounds__(256) attn_kernel(
    const float* __restrict__ q, const float* __restrict__ k,
    const float* __restrict__ v, float* __restrict__ out)
{
    __shared__ float qs[64][68];   // padded: stride 68 floats (16B aligned, bank-shifted)
    __shared__ float ks[32][68];
    __shared__ float vs[32][68];
    __shared__ float ps[64][36];

    const int tid = threadIdx.x;
    const int tx = tid & 15;
    const int ty = tid >> 4;
    const int h  = blockIdx.y;
    const int q0 = blockIdx.x * 64;

    const float* qh = q + ((size_t)h * N_TOK + q0) * D_K;
    const float* kh = k + (size_t)h * N_TOK * D_K;
    const float* vh = v + (size_t)h * N_TOK * D_K;

    // Load q tile: 64x64 floats = 1024 float4, 4 per thread.
#pragma unroll
    for (int i = 0; i < 4; i++) {
        int vv = tid + i * 256;
        int r = vv >> 4;
        int d4 = vv & 15;
        *(float4*)&qs[r][d4 * 4] = *(const float4*)(qh + r * D_K + d4 * 4);
    }

    float m_i[4], l_i[4], acc[4][4];
#pragma unroll
    for (int i = 0; i < 4; i++) {
        m_i[i] = -1e30f;
        l_i[i] = 0.0f;
#pragma unroll
        for (int j = 0; j < 4; j++) acc[i][j] = 0.0f;
    }

    const float scale = 0.125f;  // 1/sqrt(64)

    for (int kt = 0; kt < N_TOK; kt += 32) {
        __syncthreads();  // previous PV reads of ks/vs/ps done
        // Load k/v tiles: 32x64 floats = 512 float4 each, 2 per thread each.
#pragma unroll
        for (int i = 0; i < 2; i++) {
            int vv = tid + i * 256;
            int r = vv >> 4;
            int d4 = vv & 15;
            *(float4*)&ks[r][d4 * 4] = *(const float4*)(kh + (size_t)(kt + r) * D_K + d4 * 4);
            *(float4*)&vs[r][d4 * 4] = *(const float4*)(vh + (size_t)(kt + r) * D_K + d4 * 4);
        }
        __syncthreads();

        // S = q . k^T  (4 rows x 2 cols per thread)
        float s[4][2];
#pragma unroll
        for (int i = 0; i < 4; i++) { s[i][0] = 0.0f; s[i][1] = 0.0f; }
#pragma unroll
        for (int d4 = 0; d4 < 16; d4++) {
            float4 k0v = *(const float4*)&ks[tx * 2 + 0][d4 * 4];
            float4 k1v = *(const float4*)&ks[tx * 2 + 1][d4 * 4];
#pragma unroll
            for (int i = 0; i < 4; i++) {
                float4 qq = *(const float4*)&qs[ty * 4 + i][d4 * 4];
                s[i][0] += qq.x * k0v.x + qq.y * k0v.y + qq.z * k0v.z + qq.w * k0v.w;
                s[i][1] += qq.x * k1v.x + qq.y * k1v.y + qq.z * k1v.z + qq.w * k1v.w;
            }
        }

        // Online softmax update (row stats across the 16 tx lanes, shfl width 16)
#pragma unroll
        for (int i = 0; i < 4; i++) {
            float s0 = s[i][0] * scale;
            float s1 = s[i][1] * scale;
            float mx = fmaxf(s0, s1);
#pragma unroll
            for (int off = 8; off > 0; off >>= 1)
                mx = fmaxf(mx, __shfl_xor_sync(0xffffffffu, mx, off, 16));
            float mnew = fmaxf(m_i[i], mx);
            float p0 = __expf(s0 - mnew);
            float p1 = __expf(s1 - mnew);
            float sum = p0 + p1;
#pragma unroll
            for (int off = 8; off > 0; off >>= 1)
                sum += __shfl_xor_sync(0xffffffffu, sum, off, 16);
            float corr = __expf(m_i[i] - mnew);
            l_i[i] = l_i[i] * corr + sum;
            m_i[i] = mnew;
#pragma unroll
            for (int j = 0; j < 4; j++) acc[i][j] *= corr;
            ps[ty * 4 + i][tx * 2 + 0] = p0;
            ps[ty * 4 + i][tx * 2 + 1] = p1;
        }
        __syncthreads();

        // O += P @ V  (4 rows x 4 dk-cols per thread)
#pragma unroll
        for (int c = 0; c < 32; c++) {
            float4 vv4 = *(const float4*)&vs[c][tx * 4];
#pragma unroll
            for (int i = 0; i < 4; i++) {
                float p = ps[ty * 4 + i][c];
                acc[i][0] += p * vv4.x;
                acc[i][1] += p * vv4.y;
                acc[i][2] += p * vv4.z;
                acc[i][3] += p * vv4.w;
            }
        }
    }

    // Normalize and write to [n][768] concat layout
#pragma unroll
    for (int i = 0; i < 4; i++) {
        float inv = 1.0f / l_i[i];
        int row = q0 + ty * 4 + i;
#pragma unroll
        for (int j = 0; j < 4; j++)
            out[(size_t)row * D_MODEL + h * D_K + tx * 4 + j] = acc[i][j] * inv;
    }
}

// ---------------------------------------------------------------------------
// Launch
// ---------------------------------------------------------------------------
extern "C" void kernel_launch(void* const* d_in, const int* in_sizes, int n_in,
                              void* d_out, int out_size)
{
    const float* Q  = (const float*)d_in[0];
    const float* K  = (const float*)d_in[1];
    const float* V  = (const float*)d_in[2];
    const float* Wq = (const float*)d_in[3];
    const float* bq = (const float*)d_in[4];
    const float* Wk = (const float*)d_in[5];
    const float* bk = (const float*)d_in[6];
    const float* Wv = (const float*)d_in[7];
    const float* bv = (const float*)d_in[8];
    const float* Wo = (const float*)d_in[9];
    const float* bo = (const float*)d_in[10];
    float* out = (float*)d_out;

    float *qb, *kb, *vb, *ab;
    cudaGetSymbolAddress((void**)&qb, g_q);
    cudaGetSymbolAddress((void**)&kb, g_k);
    cudaGetSymbolAddress((void**)&vb, g_v);
    cudaGetSymbolAddress((void**)&ab, g_attn);

    dim3 gemmGrid(D_MODEL / BN, N_TOK / BM);  // (6, 32)

    gemm_bias_kernel<true><<<gemmGrid, 256>>>(Q, Wq, bq, qb, N_TOK, D_MODEL, D_MODEL);
    gemm_bias_kernel<true><<<gemmGrid, 256>>>(K, Wk, bk, kb, N_TOK, D_MODEL, D_MODEL);
    gemm_bias_kernel<true><<<gemmGrid, 256>>>(V, Wv, bv, vb, N_TOK, D_MODEL, D_MODEL);

    dim3 attnGrid(N_TOK / 64, N_HEADS);       // (64, 12)
    attn_kernel<<<attnGrid, 256>>>(qb, kb, vb, ab);

    gemm_bias_kernel<false><<<gemmGrid, 256>>>(ab, Wo, bo, out, N_TOK, D_MODEL, D_MODEL);
}

// round 4
// speedup vs baseline: 2.7553x; 2.7553x over previous
#include <cuda_runtime.h>
#include <cuda_bf16.h>
#include <cstdint>

// Problem constants
#define N_TOK   4096
#define D_MODEL 768
#define N_HEADS 12
#define D_K     64

// ---------------------------------------------------------------------------
// Scratch: q,k,v in [H][n][dk], attn out [n][d]
// ---------------------------------------------------------------------------
__device__ float g_q[N_HEADS * N_TOK * D_K];
__device__ float g_k[N_HEADS * N_TOK * D_K];
__device__ float g_v[N_HEADS * N_TOK * D_K];
__device__ float g_attn[N_TOK * D_MODEL];

// ---------------------------------------------------------------------------
// tf32 helpers (baseline sm_80+ PTX -- no 'a'-suffix features)
// ---------------------------------------------------------------------------
__device__ __forceinline__ uint32_t f2tf32(float f) {
    uint32_t o;
    asm("cvt.rna.tf32.f32 %0, %1;" : "=r"(o) : "f"(f));
    return o;
}

// D(16x8) += A(16x8) * B(8x8); A row-major, B col-major; fp32 accum.
__device__ __forceinline__ void mma_tf32(float c[4], const uint32_t a[4],
                                         const uint32_t b[2]) {
    asm volatile(
        "mma.sync.aligned.m16n8k8.row.col.f32.tf32.tf32.f32 "
        "{%0,%1,%2,%3}, {%4,%5,%6,%7}, {%8,%9}, {%0,%1,%2,%3};"
        : "+f"(c[0]), "+f"(c[1]), "+f"(c[2]), "+f"(c[3])
        : "r"(a[0]), "r"(a[1]), "r"(a[2]), "r"(a[3]), "r"(b[0]), "r"(b[1]));
}

// ---------------------------------------------------------------------------
// Tensor-core GEMM: C[m,o] = sum_k X[m,k]*W[o,k] + bias[o]
// Block 128x128x32, 8 warps in 2x4 grid, warp tile 64x32 (4 m-tiles x 4 n-tiles).
// MODE 0: out[m][o]. MODE 1: head-split out[h][m][t] (h=o/64, t=o%64).
// ---------------------------------------------------------------------------
#define GBM 128
#define GBN 128
#define GBK 32
#define GST 36   // smem row stride (floats): (36*g + c) % 32 = (4g+c)%32 -> conflict-free

template <int MODE>
__global__ void __launch_bounds__(256) gemm_tc_kernel(
    const float* __restrict__ X, const float* __restrict__ W,
    const float* __restrict__ bias, float* __restrict__ out,
    int M, int N, int K)
{
    __shared__ uint32_t As[GBM * GST];
    __shared__ uint32_t Bs[GBN * GST];

    const int tid  = threadIdx.x;
    const int wid  = tid >> 5;
    const int lane = tid & 31;
    const int g    = lane >> 2;   // group id (rows of fragments)
    const int c    = lane & 3;    // thread-in-group (cols of fragments)
    const int wm   = wid >> 2;    // 0..1
    const int wn   = wid & 3;     // 0..3
    const int m0   = blockIdx.y * GBM;
    const int n0   = blockIdx.x * GBN;

    float acc[4][4][4];
#pragma unroll
    for (int i = 0; i < 4; i++)
#pragma unroll
        for (int j = 0; j < 4; j++)
#pragma unroll
            for (int f = 0; f < 4; f++) acc[i][j][f] = 0.0f;

    for (int k0 = 0; k0 < K; k0 += GBK) {
        // Load tiles: 128 rows x 8 float4 each = 1024 float4, 4/thread.
#pragma unroll
        for (int i = tid; i < 1024; i += 256) {
            int r = i >> 3, c4 = (i & 7) * 4;
            float4 ta = *(const float4*)(X + (size_t)(m0 + r) * K + k0 + c4);
            uint32_t* da = &As[r * GST + c4];
            da[0] = f2tf32(ta.x); da[1] = f2tf32(ta.y);
            da[2] = f2tf32(ta.z); da[3] = f2tf32(ta.w);
            float4 tb = *(const float4*)(W + (size_t)(n0 + r) * K + k0 + c4);
            uint32_t* db = &Bs[r * GST + c4];
            db[0] = f2tf32(tb.x); db[1] = f2tf32(tb.y);
            db[2] = f2tf32(tb.z); db[3] = f2tf32(tb.w);
        }
        __syncthreads();

#pragma unroll
        for (int s = 0; s < 4; s++) {
            const int c0 = s * 8;
            uint32_t a[4][4], b[4][2];
#pragma unroll
            for (int mt = 0; mt < 4; mt++) {
                int r = wm * 64 + mt * 16 + g;
                a[mt][0] = As[r * GST + c0 + c];
                a[mt][1] = As[(r + 8) * GST + c0 + c];
                a[mt][2] = As[r * GST + c0 + c + 4];
                a[mt][3] = As[(r + 8) * GST + c0 + c + 4];
            }
#pragma unroll
            for (int nt = 0; nt < 4; nt++) {
                int n = wn * 32 + nt * 8 + g;
                b[nt][0] = Bs[n * GST + c0 + c];
                b[nt][1] = Bs[n * GST + c0 + c + 4];
            }
#pragma unroll
            for (int mt = 0; mt < 4; mt++)
#pragma unroll
                for (int nt = 0; nt < 4; nt++)
                    mma_tf32(acc[mt][nt], a[mt], b[nt]);
        }
        __syncthreads();
    }

    // Epilogue: bias + store (two rows per fragment, col pair contiguous)
#pragma unroll
    for (int nt = 0; nt < 4; nt++) {
        int col = n0 + wn * 32 + nt * 8 + 2 * c;
        float b0 = bias[col], b1 = bias[col + 1];
#pragma unroll
        for (int mt = 0; mt < 4; mt++) {
            int row = m0 + wm * 64 + mt * 16 + g;
            float v00 = acc[mt][nt][0] + b0, v01 = acc[mt][nt][1] + b1;
            float v10 = acc[mt][nt][2] + b0, v11 = acc[mt][nt][3] + b1;
            if (MODE == 1) {
                int h = col >> 6, t = col & 63;
                float2* p0 = (float2*)&out[((size_t)h * M + row) * D_K + t];
                float2* p1 = (float2*)&out[((size_t)h * M + row + 8) * D_K + t];
                *p0 = make_float2(v00, v01);
                *p1 = make_float2(v10, v11);
            } else {
                float2* p0 = (float2*)&out[(size_t)row * N + col];
                float2* p1 = (float2*)&out[(size_t)(row + 8) * N + col];
                *p0 = make_float2(v00, v01);
                *p1 = make_float2(v10, v11);
            }
        }
    }
}

// ---------------------------------------------------------------------------
// Tensor-core flash attention (tf32 mma.sync, unnormalized-exp softmax).
// Grid (32, 12), 256 threads. Per CTA: 1 head, 128 q rows; kv tiles of 64.
// Each warp owns 16 q rows for the entire kernel; Q fragments live in regs.
// SMEM (dynamic): Qp[128*68] (reused as P after Q frags extracted),
//                 Ks[64*68], Vs[64*68]  -> 17408 words = 69,632 B.
// ---------------------------------------------------------------------------
#define AST 68   // row stride: (68g + c)%32 = (4g+c)%32 -> conflict-free frags

__global__ void __launch_bounds__(256) attn_tc_kernel(
    const float* __restrict__ q, const float* __restrict__ k,
    const float* __restrict__ v, float* __restrict__ out)
{
    extern __shared__ uint32_t sh[];
    uint32_t* Qp = sh;                 // 128*AST, later reused for P
    uint32_t* Ks = sh + 128 * AST;     // 64*AST
    uint32_t* Vs = Ks + 64 * AST;      // 64*AST

    const int tid  = threadIdx.x;
    const int wid  = tid >> 5;
    const int lane = tid & 31;
    const int g    = lane >> 2;
    const int c    = lane & 3;
    const int wr   = wid * 16;         // this warp's q-row block
    const int h    = blockIdx.y;
    const int q0   = blockIdx.x * 128;

    // Load Q tile (scaled by 1/sqrt(64)=0.125), convert to tf32.
    const float* qh = q + ((size_t)h * N_TOK + q0) * D_K;
#pragma unroll
    for (int i = tid; i < 2048; i += 256) {  // 128 rows x 16 float4
        int r = i >> 4, c4 = (i & 15) * 4;
        float4 t = *(const float4*)(qh + (size_t)r * D_K + c4);
        uint32_t* d = &Qp[r * AST + c4];
        d[0] = f2tf32(t.x * 0.125f); d[1] = f2tf32(t.y * 0.125f);
        d[2] = f2tf32(t.z * 0.125f); d[3] = f2tf32(t.w * 0.125f);
    }
    __syncthreads();

    // Extract persistent Q fragments (8 k-steps over dk=64).
    uint32_t qa[8][4];
#pragma unroll
    for (int s = 0; s < 8; s++) {
        int c0 = s * 8;
        qa[s][0] = Qp[(wr + g) * AST + c0 + c];
        qa[s][1] = Qp[(wr + g + 8) * AST + c0 + c];
        qa[s][2] = Qp[(wr + g) * AST + c0 + c + 4];
        qa[s][3] = Qp[(wr + g + 8) * AST + c0 + c + 4];
    }
    __syncthreads();  // all warps done reading Q before it is reused as P

    float o[8][4];
#pragma unroll
    for (int nt = 0; nt < 8; nt++)
#pragma unroll
        for (int f = 0; f < 4; f++) o[nt][f] = 0.0f;
    float ls0 = 0.0f, ls1 = 0.0f;  // unnormalized row sums (rows wr+g, wr+g+8)

    const float* kh = k + (size_t)h * N_TOK * D_K;
    const float* vh = v + (size_t)h * N_TOK * D_K;

    for (int kt = 0; kt < N_TOK; kt += 64) {
        // Load K/V tiles: 64 rows x 16 float4 each.
#pragma unroll
        for (int i = tid; i < 1024; i += 256) {
            int r = i >> 4, c4 = (i & 15) * 4;
            float4 tk = *(const float4*)(kh + (size_t)(kt + r) * D_K + c4);
            uint32_t* dk_ = &Ks[r * AST + c4];
            dk_[0] = f2tf32(tk.x); dk_[1] = f2tf32(tk.y);
            dk_[2] = f2tf32(tk.z); dk_[3] = f2tf32(tk.w);
            float4 tv = *(const float4*)(vh + (size_t)(kt + r) * D_K + c4);
            uint32_t* dv = &Vs[r * AST + c4];
            dv[0] = f2tf32(tv.x); dv[1] = f2tf32(tv.y);
            dv[2] = f2tf32(tv.z); dv[3] = f2tf32(tv.w);
        }
        __syncthreads();

        // S = Q.K^T for this warp's 16 rows x 64 kv cols; exp; store P.
#pragma unroll
        for (int nt = 0; nt < 8; nt++) {
            float sfr[4] = {0.0f, 0.0f, 0.0f, 0.0f};
#pragma unroll
            for (int s = 0; s < 8; s++) {
                uint32_t b[2];
                int n = nt * 8 + g;
                b[0] = Ks[n * AST + s * 8 + c];
                b[1] = Ks[n * AST + s * 8 + c + 4];
                mma_tf32(sfr, qa[s], b);
            }
            float p0 = __expf(sfr[0]), p1 = __expf(sfr[1]);
            float p2 = __expf(sfr[2]), p3 = __expf(sfr[3]);
            ls0 += p0 + p1;
            ls1 += p2 + p3;
            int col = nt * 8 + 2 * c;
            uint32_t* pp0 = &Qp[(wr + g) * AST + col];
            uint32_t* pp1 = &Qp[(wr + g + 8) * AST + col];
            pp0[0] = f2tf32(p0); pp0[1] = f2tf32(p1);
            pp1[0] = f2tf32(p2); pp1[1] = f2tf32(p3);
        }
        __syncwarp();  // P rows are warp-private; only intra-warp visibility needed

        // O += P.V  (k = 64 kv, n = 64 dk)
#pragma unroll
        for (int s = 0; s < 8; s++) {
            uint32_t pa[4];
            int c0 = s * 8;
            pa[0] = Qp[(wr + g) * AST + c0 + c];
            pa[1] = Qp[(wr + g + 8) * AST + c0 + c];
            pa[2] = Qp[(wr + g) * AST + c0 + c + 4];
            pa[3] = Qp[(wr + g + 8) * AST + c0 + c + 4];
#pragma unroll
            for (int nt = 0; nt < 8; nt++) {
                uint32_t b[2];
                b[0] = Vs[(c0 + c) * AST + nt * 8 + g];
                b[1] = Vs[(c0 + c + 4) * AST + nt * 8 + g];
                mma_tf32(o[nt], pa, b);
            }
        }
        __syncthreads();  // protect Ks/Vs before next iteration's loads
    }

    // Reduce row sums across the 4-lane quad.
    ls0 += __shfl_xor_sync(0xffffffffu, ls0, 1);
    ls0 += __shfl_xor_sync(0xffffffffu, ls0, 2);
    ls1 += __shfl_xor_sync(0xffffffffu, ls1, 1);
    ls1 += __shfl_xor_sync(0xffffffffu, ls1, 2);
    const float inv0 = 1.0f / ls0;
    const float inv1 = 1.0f / ls1;

    // Write O to [n][768] concat-head layout.
#pragma unroll
    for (int nt = 0; nt < 8; nt++) {
        int col = h * D_K + nt * 8 + 2 * c;
        float2* p0 = (float2*)&out[(size_t)(q0 + wr + g) * D_MODEL + col];
        float2* p1 = (float2*)&out[(size_t)(q0 + wr + g + 8) * D_MODEL + col];
        *p0 = make_float2(o[nt][0] * inv0, o[nt][1] * inv0);
        *p1 = make_float2(o[nt][2] * inv1, o[nt][3] * inv1);
    }
}

#define ATT_SMEM_BYTES ((128 * AST + 64 * AST + 64 * AST) * 4)

// ---------------------------------------------------------------------------
// Launch
// ---------------------------------------------------------------------------
extern "C" void kernel_launch(void* const* d_in, const int* in_sizes, int n_in,
                              void* d_out, int out_size)
{
    const float* Q  = (const float*)d_in[0];
    const float* K  = (const float*)d_in[1];
    const float* V  = (const float*)d_in[2];
    const float* Wq = (const float*)d_in[3];
    const float* bq = (const float*)d_in[4];
    const float* Wk = (const float*)d_in[5];
    const float* bk = (const float*)d_in[6];
    const float* Wv = (const float*)d_in[7];
    const float* bv = (const float*)d_in[8];
    const float* Wo = (const float*)d_in[9];
    const float* bo = (const float*)d_in[10];
    float* out = (float*)d_out;

    float *qb, *kb, *vb, *ab;
    cudaGetSymbolAddress((void**)&qb, g_q);
    cudaGetSymbolAddress((void**)&kb, g_k);
    cudaGetSymbolAddress((void**)&vb, g_v);
    cudaGetSymbolAddress((void**)&ab, g_attn);

    // Idempotent, capture-safe (not a stream op). No static guard per harness rules.
    cudaFuncSetAttribute(attn_tc_kernel,
                         cudaFuncAttributeMaxDynamicSharedMemorySize,
                         ATT_SMEM_BYTES);

    dim3 gemmGrid(D_MODEL / GBN, N_TOK / GBM);  // (6, 32)

    gemm_tc_kernel<1><<<gemmGrid, 256>>>(Q, Wq, bq, qb, N_TOK, D_MODEL, D_MODEL);
    gemm_tc_kernel<1><<<gemmGrid, 256>>>(K, Wk, bk, kb, N_TOK, D_MODEL, D_MODEL);
    gemm_tc_kernel<1><<<gemmGrid, 256>>>(V, Wv, bv, vb, N_TOK, D_MODEL, D_MODEL);

    dim3 attnGrid(N_TOK / 128, N_HEADS);        // (32, 12)
    attn_tc_kernel<<<attnGrid, 256, ATT_SMEM_BYTES>>>(qb, kb, vb, ab);

    gemm_tc_kernel<0><<<gemmGrid, 256>>>(ab, Wo, bo, out, N_TOK, D_MODEL, D_MODEL);
}

// round 6
// speedup vs baseline: 3.4426x; 1.2495x over previous
#include <cuda_runtime.h>
#include <cuda_bf16.h>
#include <cstdint>

// Problem constants
#define N_TOK   4096
#define D_MODEL 768
#define N_HEADS 12
#define D_K     64

// ---------------------------------------------------------------------------
// Scratch: q,k,v in [H][n][dk], attn out [n][d]
// ---------------------------------------------------------------------------
__device__ float g_q[N_HEADS * N_TOK * D_K];
__device__ float g_k[N_HEADS * N_TOK * D_K];
__device__ float g_v[N_HEADS * N_TOK * D_K];
__device__ float g_attn[N_TOK * D_MODEL];

// ---------------------------------------------------------------------------
// Helpers (baseline sm_80+ PTX only)
// ---------------------------------------------------------------------------
__device__ __forceinline__ uint32_t f2tf32(float f) {
    uint32_t o;
    asm("cvt.rna.tf32.f32 %0, %1;" : "=r"(o) : "f"(f));
    return o;
}
__device__ __forceinline__ uint32_t u2tf32(uint32_t w) {
    return f2tf32(__uint_as_float(w));
}
__device__ __forceinline__ uint32_t smem_u32(const void* p) {
    uint32_t a;
    asm("{ .reg .u64 t; cvta.to.shared.u64 t, %1; cvt.u32.u64 %0, t; }" : "=r"(a) : "l"(p));
    return a;
}
#define CP_ASYNC16(dst_u32, src) \
    asm volatile("cp.async.cg.shared.global [%0], [%1], 16;" \
                 :: "r"(dst_u32), "l"(src) : "memory")
#define CP_COMMIT() asm volatile("cp.async.commit_group;" ::: "memory")
#define CP_WAIT1()  asm volatile("cp.async.wait_group 1;" ::: "memory")
#define CP_WAIT0()  asm volatile("cp.async.wait_group 0;" ::: "memory")

// D(16x8) += A(16x8) * B(8x8); A row-major, B col-major; fp32 accum.
__device__ __forceinline__ void mma_tf32(float c[4], const uint32_t a[4],
                                         const uint32_t b[2]) {
    asm volatile(
        "mma.sync.aligned.m16n8k8.row.col.f32.tf32.tf32.f32 "
        "{%0,%1,%2,%3}, {%4,%5,%6,%7}, {%8,%9}, {%0,%1,%2,%3};"
        : "+f"(c[0]), "+f"(c[1]), "+f"(c[2]), "+f"(c[3])
        : "r"(a[0]), "r"(a[1]), "r"(a[2]), "r"(a[3]), "r"(b[0]), "r"(b[1]));
}

// ---------------------------------------------------------------------------
// Tensor-core GEMM: C[m,o] = sum_k X[m,k]*W[o,k] + bias[o]
// Block 128x128x32, 8 warps (2x4), warp tile 64x32. cp.async double-buffered.
// MODE 0: out[m][o]. MODE 1: head-split out[h][m][t] (h=o/64, t=o%64).
// Dynamic smem: 2 buffers x (As 128*36 + Bs 128*36) words = 73,728 B.
// ---------------------------------------------------------------------------
#define GBM 128
#define GBN 128
#define GBK 32
#define GST 36   // (36*g + c) % 32 = (4g+c)%32 -> conflict-free fragment loads
#define GEMM_SMEM_BYTES (2 * 2 * GBM * GST * 4)

template <int MODE>
__global__ void __launch_bounds__(256) gemm_tc_kernel(
    const float* __restrict__ X, const float* __restrict__ W,
    const float* __restrict__ bias, float* __restrict__ out,
    int M, int N, int K)
{
    extern __shared__ uint32_t gsh[];
    // buffer b: As at gsh + b*2*128*GST, Bs right after As
    const int tid  = threadIdx.x;
    const int wid  = tid >> 5;
    const int lane = tid & 31;
    const int g    = lane >> 2;
    const int c    = lane & 3;
    const int wm   = wid >> 2;
    const int wn   = wid & 3;
    const int m0   = blockIdx.y * GBM;
    const int n0   = blockIdx.x * GBN;

    const uint32_t sbase = smem_u32(gsh);

    float acc[4][4][4];
#pragma unroll
    for (int i = 0; i < 4; i++)
#pragma unroll
        for (int j = 0; j < 4; j++)
#pragma unroll
            for (int f = 0; f < 4; f++) acc[i][j][f] = 0.0f;

    const int NIT = K / GBK;  // 24

    // Issue tile 0
    {
        uint32_t as = sbase, bs = sbase + GBM * GST * 4;
#pragma unroll
        for (int i = tid; i < 1024; i += 256) {
            int r = i >> 3, c4 = (i & 7) * 4;
            CP_ASYNC16(as + (r * GST + c4) * 4, X + (size_t)(m0 + r) * K + c4);
            CP_ASYNC16(bs + (r * GST + c4) * 4, W + (size_t)(n0 + r) * K + c4);
        }
        CP_COMMIT();
    }

    for (int it = 0; it < NIT; ++it) {
        const int cur = it & 1;
        if (it + 1 < NIT) {
            const int k0 = (it + 1) * GBK;
            uint32_t as = sbase + (size_t)(cur ^ 1) * 2 * GBM * GST * 4;
            uint32_t bs = as + GBM * GST * 4;
#pragma unroll
            for (int i = tid; i < 1024; i += 256) {
                int r = i >> 3, c4 = (i & 7) * 4;
                CP_ASYNC16(as + (r * GST + c4) * 4, X + (size_t)(m0 + r) * K + k0 + c4);
                CP_ASYNC16(bs + (r * GST + c4) * 4, W + (size_t)(n0 + r) * K + k0 + c4);
            }
            CP_COMMIT();
            CP_WAIT1();
        } else {
            CP_WAIT0();
        }
        __syncthreads();

        const uint32_t* As = gsh + (size_t)cur * 2 * GBM * GST;
        const uint32_t* Bs = As + GBM * GST;

#pragma unroll
        for (int s = 0; s < 4; s++) {
            const int c0 = s * 8;
            uint32_t a[4][4], b[4][2];
#pragma unroll
            for (int mt = 0; mt < 4; mt++) {
                int r = wm * 64 + mt * 16 + g;
                a[mt][0] = u2tf32(As[r * GST + c0 + c]);
                a[mt][1] = u2tf32(As[(r + 8) * GST + c0 + c]);
                a[mt][2] = u2tf32(As[r * GST + c0 + c + 4]);
                a[mt][3] = u2tf32(As[(r + 8) * GST + c0 + c + 4]);
            }
#pragma unroll
            for (int nt = 0; nt < 4; nt++) {
                int n = wn * 32 + nt * 8 + g;
                b[nt][0] = u2tf32(Bs[n * GST + c0 + c]);
                b[nt][1] = u2tf32(Bs[n * GST + c0 + c + 4]);
            }
#pragma unroll
            for (int mt = 0; mt < 4; mt++)
#pragma unroll
                for (int nt = 0; nt < 4; nt++)
                    mma_tf32(acc[mt][nt], a[mt], b[nt]);
        }
        __syncthreads();
    }

    // Epilogue: bias + store
#pragma unroll
    for (int nt = 0; nt < 4; nt++) {
        int col = n0 + wn * 32 + nt * 8 + 2 * c;
        float b0 = bias[col], b1 = bias[col + 1];
#pragma unroll
        for (int mt = 0; mt < 4; mt++) {
            int row = m0 + wm * 64 + mt * 16 + g;
            float v00 = acc[mt][nt][0] + b0, v01 = acc[mt][nt][1] + b1;
            float v10 = acc[mt][nt][2] + b0, v11 = acc[mt][nt][3] + b1;
            if (MODE == 1) {
                int h = col >> 6, t = col & 63;
                float2* p0 = (float2*)&out[((size_t)h * M + row) * D_K + t];
                float2* p1 = (float2*)&out[((size_t)h * M + row + 8) * D_K + t];
                *p0 = make_float2(v00, v01);
                *p1 = make_float2(v10, v11);
            } else {
                float2* p0 = (float2*)&out[(size_t)row * N + col];
                float2* p1 = (float2*)&out[(size_t)(row + 8) * N + col];
                *p0 = make_float2(v00, v01);
                *p1 = make_float2(v10, v11);
            }
        }
    }
}

// ---------------------------------------------------------------------------
// Tensor-core flash attention (tf32 mma.sync, unnormalized-exp softmax),
// cp.async double-buffered K/V tiles.
// Grid (32, 12), 256 threads. Per CTA: 1 head, 128 q rows; kv tiles of 64.
// SMEM layout (uint32 words):
//   Qp : 128*68            (Q frags then reused as P; tf32 words)
//   Ks : 2 x 64*68         (raw f32, cvt at fragment load)
//   Vs : 2 x 64*72         (stride 72 -> conflict-free B-frag loads)
// ---------------------------------------------------------------------------
#define AST 68   // Q/P and K row stride
#define VST 72   // V row stride: bank = (8c+g)%32, bijective -> conflict-free
#define ATT_QW   (128 * AST)
#define ATT_KW   (64 * AST)
#define ATT_VW   (64 * VST)
#define ATT_SMEM_BYTES ((ATT_QW + 2 * ATT_KW + 2 * ATT_VW) * 4)

__global__ void __launch_bounds__(256) attn_tc_kernel(
    const float* __restrict__ q, const float* __restrict__ k,
    const float* __restrict__ v, float* __restrict__ out)
{
    extern __shared__ uint32_t sh[];
    uint32_t* Qp  = sh;
    uint32_t* Ksb[2] = { sh + ATT_QW, sh + ATT_QW + ATT_KW };
    uint32_t* Vsb[2] = { sh + ATT_QW + 2 * ATT_KW, sh + ATT_QW + 2 * ATT_KW + ATT_VW };

    const int tid  = threadIdx.x;
    const int wid  = tid >> 5;
    const int lane = tid & 31;
    const int g    = lane >> 2;
    const int c    = lane & 3;
    const int wr   = wid * 16;
    const int h    = blockIdx.y;
    const int q0   = blockIdx.x * 128;

    const float* kh = k + (size_t)h * N_TOK * D_K;
    const float* vh = v + (size_t)h * N_TOK * D_K;

    // Issue kv tile 0 FIRST so it overlaps the Q prologue.
    {
        uint32_t ks = smem_u32(Ksb[0]), vs = smem_u32(Vsb[0]);
#pragma unroll
        for (int i = tid; i < 1024; i += 256) {
            int r = i >> 4, c4 = (i & 15) * 4;
            CP_ASYNC16(ks + (r * AST + c4) * 4, kh + (size_t)r * D_K + c4);
            CP_ASYNC16(vs + (r * VST + c4) * 4, vh + (size_t)r * D_K + c4);
        }
        CP_COMMIT();
    }

    // Load Q tile (scaled by 0.125), convert to tf32.
    const float* qh = q + ((size_t)h * N_TOK + q0) * D_K;
#pragma unroll
    for (int i = tid; i < 2048; i += 256) {
        int r = i >> 4, c4 = (i & 15) * 4;
        float4 t = *(const float4*)(qh + (size_t)r * D_K + c4);
        uint32_t* d = &Qp[r * AST + c4];
        d[0] = f2tf32(t.x * 0.125f); d[1] = f2tf32(t.y * 0.125f);
        d[2] = f2tf32(t.z * 0.125f); d[3] = f2tf32(t.w * 0.125f);
    }
    __syncthreads();

    // Persistent Q fragments.
    uint32_t qa[8][4];
#pragma unroll
    for (int s = 0; s < 8; s++) {
        int c0 = s * 8;
        qa[s][0] = Qp[(wr + g) * AST + c0 + c];
        qa[s][1] = Qp[(wr + g + 8) * AST + c0 + c];
        qa[s][2] = Qp[(wr + g) * AST + c0 + c + 4];
        qa[s][3] = Qp[(wr + g + 8) * AST + c0 + c + 4];
    }
    __syncthreads();  // Q fully read before Qp is reused as P

    float o[8][4];
#pragma unroll
    for (int nt = 0; nt < 8; nt++)
#pragma unroll
        for (int f = 0; f < 4; f++) o[nt][f] = 0.0f;
    float ls0 = 0.0f, ls1 = 0.0f;

    const int NIT = N_TOK / 64;  // 64 iterations of 64-row kv tiles
    for (int it = 0; it < NIT; ++it) {
        const int cur = it & 1;
        if (it + 1 < NIT) {
            const int kt = (it + 1) * 64;
            uint32_t ks = smem_u32(Ksb[cur ^ 1]), vs = smem_u32(Vsb[cur ^ 1]);
#pragma unroll
            for (int i = tid; i < 1024; i += 256) {
                int r = i >> 4, c4 = (i & 15) * 4;
                CP_ASYNC16(ks + (r * AST + c4) * 4, kh + (size_t)(kt + r) * D_K + c4);
                CP_ASYNC16(vs + (r * VST + c4) * 4, vh + (size_t)(kt + r) * D_K + c4);
            }
            CP_COMMIT();
            CP_WAIT1();
        } else {
            CP_WAIT0();
        }
        __syncthreads();

        const uint32_t* Ks = Ksb[cur];
        const uint32_t* Vs = Vsb[cur];

        // S = Q.K^T (warp's 16 rows x 64 kv); exp; store P (tf32) into Qp.
#pragma unroll
        for (int nt = 0; nt < 8; nt++) {
            float sfr[4] = {0.0f, 0.0f, 0.0f, 0.0f};
#pragma unroll
            for (int s = 0; s < 8; s++) {
                uint32_t b[2];
                int n = nt * 8 + g;
                b[0] = u2tf32(Ks[n * AST + s * 8 + c]);
                b[1] = u2tf32(Ks[n * AST + s * 8 + c + 4]);
                mma_tf32(sfr, qa[s], b);
            }
            float p0 = __expf(sfr[0]), p1 = __expf(sfr[1]);
            float p2 = __expf(sfr[2]), p3 = __expf(sfr[3]);
            ls0 += p0 + p1;
            ls1 += p2 + p3;
            int col = nt * 8 + 2 * c;
            uint32_t* pp0 = &Qp[(wr + g) * AST + col];
            uint32_t* pp1 = &Qp[(wr + g + 8) * AST + col];
            pp0[0] = f2tf32(p0); pp0[1] = f2tf32(p1);
            pp1[0] = f2tf32(p2); pp1[1] = f2tf32(p3);
        }
        __syncwarp();  // P rows are warp-private

        // O += P.V
#pragma unroll
        for (int s = 0; s < 8; s++) {
            uint32_t pa[4];
            int c0 = s * 8;
            pa[0] = Qp[(wr + g) * AST + c0 + c];
            pa[1] = Qp[(wr + g + 8) * AST + c0 + c];
            pa[2] = Qp[(wr + g) * AST + c0 + c + 4];
            pa[3] = Qp[(wr + g + 8) * AST + c0 + c + 4];
#pragma unroll
            for (int nt = 0; nt < 8; nt++) {
                uint32_t b[2];
                b[0] = u2tf32(Vs[(c0 + c) * VST + nt * 8 + g]);
                b[1] = u2tf32(Vs[(c0 + c + 4) * VST + nt * 8 + g]);
                mma_tf32(o[nt], pa, b);
            }
        }
        __syncthreads();  // all reads of buf[cur] done before it+1 overwrites it
    }

    // Reduce row sums across the 4-lane quad.
    ls0 += __shfl_xor_sync(0xffffffffu, ls0, 1);
    ls0 += __shfl_xor_sync(0xffffffffu, ls0, 2);
    ls1 += __shfl_xor_sync(0xffffffffu, ls1, 1);
    ls1 += __shfl_xor_sync(0xffffffffu, ls1, 2);
    const float inv0 = 1.0f / ls0;
    const float inv1 = 1.0f / ls1;

    // Write O to [n][768] concat-head layout.
#pragma unroll
    for (int nt = 0; nt < 8; nt++) {
        int col = h * D_K + nt * 8 + 2 * c;
        float2* p0 = (float2*)&out[(size_t)(q0 + wr + g) * D_MODEL + col];
        float2* p1 = (float2*)&out[(size_t)(q0 + wr + g + 8) * D_MODEL + col];
        *p0 = make_float2(o[nt][0] * inv0, o[nt][1] * inv0);
        *p1 = make_float2(o[nt][2] * inv1, o[nt][3] * inv1);
    }
}

// ---------------------------------------------------------------------------
// Launch
// ---------------------------------------------------------------------------
extern "C" void kernel_launch(void* const* d_in, const int* in_sizes, int n_in,
                              void* d_out, int out_size)
{
    const float* Q  = (const float*)d_in[0];
    const float* K  = (const float*)d_in[1];
    const float* V  = (const float*)d_in[2];
    const float* Wq = (const float*)d_in[3];
    const float* bq = (const float*)d_in[4];
    const float* Wk = (const float*)d_in[5];
    const float* bk = (const float*)d_in[6];
    const float* Wv = (const float*)d_in[7];
    const float* bv = (const float*)d_in[8];
    const float* Wo = (const float*)d_in[9];
    const float* bo = (const float*)d_in[10];
    float* out = (float*)d_out;

    float *qb, *kb, *vb, *ab;
    cudaGetSymbolAddress((void**)&qb, g_q);
    cudaGetSymbolAddress((void**)&kb, g_k);
    cudaGetSymbolAddress((void**)&vb, g_v);
    cudaGetSymbolAddress((void**)&ab, g_attn);

    // Idempotent, capture-safe (not stream ops).
    cudaFuncSetAttribute(attn_tc_kernel,
                         cudaFuncAttributeMaxDynamicSharedMemorySize, ATT_SMEM_BYTES);
    cudaFuncSetAttribute(gemm_tc_kernel<0>,
                         cudaFuncAttributeMaxDynamicSharedMemorySize, GEMM_SMEM_BYTES);
    cudaFuncSetAttribute(gemm_tc_kernel<1>,
                         cudaFuncAttributeMaxDynamicSharedMemorySize, GEMM_SMEM_BYTES);

    dim3 gemmGrid(D_MODEL / GBN, N_TOK / GBM);  // (6, 32)

    gemm_tc_kernel<1><<<gemmGrid, 256, GEMM_SMEM_BYTES>>>(Q, Wq, bq, qb, N_TOK, D_MODEL, D_MODEL);
    gemm_tc_kernel<1><<<gemmGrid, 256, GEMM_SMEM_BYTES>>>(K, Wk, bk, kb, N_TOK, D_MODEL, D_MODEL);
    gemm_tc_kernel<1><<<gemmGrid, 256, GEMM_SMEM_BYTES>>>(V, Wv, bv, vb, N_TOK, D_MODEL, D_MODEL);

    dim3 attnGrid(N_TOK / 128, N_HEADS);        // (32, 12)
    attn_tc_kernel<<<attnGrid, 256, ATT_SMEM_BYTES>>>(qb, kb, vb, ab);

    gemm_tc_kernel<0><<<gemmGrid, 256, GEMM_SMEM_BYTES>>>(ab, Wo, bo, out, N_TOK, D_MODEL, D_MODEL);
}

// round 7
// speedup vs baseline: 3.4436x; 1.0003x over previous
#include <cuda_runtime.h>
#include <cuda_bf16.h>
#include <cstdint>

// Problem constants
#define N_TOK   4096
#define D_MODEL 768
#define N_HEADS 12
#define D_K     64

// ---------------------------------------------------------------------------
// Scratch: q,k,v in [H][n][dk], attn out [n][d]
// ---------------------------------------------------------------------------
__device__ float g_q[N_HEADS * N_TOK * D_K];
__device__ float g_k[N_HEADS * N_TOK * D_K];
__device__ float g_v[N_HEADS * N_TOK * D_K];
__device__ float g_attn[N_TOK * D_MODEL];

// ---------------------------------------------------------------------------
// Helpers (baseline sm_80+ PTX only)
// ---------------------------------------------------------------------------
__device__ __forceinline__ uint32_t f2tf32(float f) {
    uint32_t o;
    asm("cvt.rna.tf32.f32 %0, %1;" : "=r"(o) : "f"(f));
    return o;
}
__device__ __forceinline__ uint32_t u2tf32(uint32_t w) {
    return f2tf32(__uint_as_float(w));
}
__device__ __forceinline__ uint32_t smem_u32(const void* p) {
    uint32_t a;
    asm("{ .reg .u64 t; cvta.to.shared.u64 t, %1; cvt.u32.u64 %0, t; }" : "=r"(a) : "l"(p));
    return a;
}
#define CP_ASYNC16(dst_u32, src) \
    asm volatile("cp.async.cg.shared.global [%0], [%1], 16;" \
                 :: "r"(dst_u32), "l"(src) : "memory")
#define CP_COMMIT() asm volatile("cp.async.commit_group;" ::: "memory")
#define CP_WAIT1()  asm volatile("cp.async.wait_group 1;" ::: "memory")
#define CP_WAIT0()  asm volatile("cp.async.wait_group 0;" ::: "memory")

// D(16x8) += A(16x8) * B(8x8); A row-major, B col-major; fp32 accum.
__device__ __forceinline__ void mma_tf32(float c[4], const uint32_t a[4],
                                         const uint32_t b[2]) {
    asm volatile(
        "mma.sync.aligned.m16n8k8.row.col.f32.tf32.tf32.f32 "
        "{%0,%1,%2,%3}, {%4,%5,%6,%7}, {%8,%9}, {%0,%1,%2,%3};"
        : "+f"(c[0]), "+f"(c[1]), "+f"(c[2]), "+f"(c[3])
        : "r"(a[0]), "r"(a[1]), "r"(a[2]), "r"(a[3]), "r"(b[0]), "r"(b[1]));
}

// ---------------------------------------------------------------------------
// Tensor-core GEMM: C[m,o] = sum_k X[m,k]*W[o,k] + bias[o]
// Block 128x128x32, 8 warps (2x4), warp tile 64x32. cp.async double-buffered.
// MODE 0: out[m][o]. MODE 1: head-split out[h][m][t] (h=o/64, t=o%64).
// Dynamic smem: 2 buffers x (As 128*36 + Bs 128*36) words = 73,728 B.
// ---------------------------------------------------------------------------
#define GBM 128
#define GBN 128
#define GBK 32
#define GST 36   // (36*g + c) % 32 = (4g+c)%32 -> conflict-free fragment loads
#define GEMM_SMEM_BYTES (2 * 2 * GBM * GST * 4)

template <int MODE>
__global__ void __launch_bounds__(256) gemm_tc_kernel(
    const float* __restrict__ X, const float* __restrict__ W,
    const float* __restrict__ bias, float* __restrict__ out,
    int M, int N, int K)
{
    extern __shared__ uint32_t gsh[];
    // buffer b: As at gsh + b*2*128*GST, Bs right after As
    const int tid  = threadIdx.x;
    const int wid  = tid >> 5;
    const int lane = tid & 31;
    const int g    = lane >> 2;
    const int c    = lane & 3;
    const int wm   = wid >> 2;
    const int wn   = wid & 3;
    const int m0   = blockIdx.y * GBM;
    const int n0   = blockIdx.x * GBN;

    const uint32_t sbase = smem_u32(gsh);

    float acc[4][4][4];
#pragma unroll
    for (int i = 0; i < 4; i++)
#pragma unroll
        for (int j = 0; j < 4; j++)
#pragma unroll
            for (int f = 0; f < 4; f++) acc[i][j][f] = 0.0f;

    const int NIT = K / GBK;  // 24

    // Issue tile 0
    {
        uint32_t as = sbase, bs = sbase + GBM * GST * 4;
#pragma unroll
        for (int i = tid; i < 1024; i += 256) {
            int r = i >> 3, c4 = (i & 7) * 4;
            CP_ASYNC16(as + (r * GST + c4) * 4, X + (size_t)(m0 + r) * K + c4);
            CP_ASYNC16(bs + (r * GST + c4) * 4, W + (size_t)(n0 + r) * K + c4);
        }
        CP_COMMIT();
    }

    for (int it = 0; it < NIT; ++it) {
        const int cur = it & 1;
        if (it + 1 < NIT) {
            const int k0 = (it + 1) * GBK;
            uint32_t as = sbase + (size_t)(cur ^ 1) * 2 * GBM * GST * 4;
            uint32_t bs = as + GBM * GST * 4;
#pragma unroll
            for (int i = tid; i < 1024; i += 256) {
                int r = i >> 3, c4 = (i & 7) * 4;
                CP_ASYNC16(as + (r * GST + c4) * 4, X + (size_t)(m0 + r) * K + k0 + c4);
                CP_ASYNC16(bs + (r * GST + c4) * 4, W + (size_t)(n0 + r) * K + k0 + c4);
            }
            CP_COMMIT();
            CP_WAIT1();
        } else {
            CP_WAIT0();
        }
        __syncthreads();

        const uint32_t* As = gsh + (size_t)cur * 2 * GBM * GST;
        const uint32_t* Bs = As + GBM * GST;

#pragma unroll
        for (int s = 0; s < 4; s++) {
            const int c0 = s * 8;
            uint32_t a[4][4], b[4][2];
#pragma unroll
            for (int mt = 0; mt < 4; mt++) {
                int r = wm * 64 + mt * 16 + g;
                a[mt][0] = u2tf32(As[r * GST + c0 + c]);
                a[mt][1] = u2tf32(As[(r + 8) * GST + c0 + c]);
                a[mt][2] = u2tf32(As[r * GST + c0 + c + 4]);
                a[mt][3] = u2tf32(As[(r + 8) * GST + c0 + c + 4]);
            }
#pragma unroll
            for (int nt = 0; nt < 4; nt++) {
                int n = wn * 32 + nt * 8 + g;
                b[nt][0] = u2tf32(Bs[n * GST + c0 + c]);
                b[nt][1] = u2tf32(Bs[n * GST + c0 + c + 4]);
            }
#pragma unroll
            for (int mt = 0; mt < 4; mt++)
#pragma unroll
                for (int nt = 0; nt < 4; nt++)
                    mma_tf32(acc[mt][nt], a[mt], b[nt]);
        }
        __syncthreads();
    }

    // Epilogue: bias + store
#pragma unroll
    for (int nt = 0; nt < 4; nt++) {
        int col = n0 + wn * 32 + nt * 8 + 2 * c;
        float b0 = bias[col], b1 = bias[col + 1];
#pragma unroll
        for (int mt = 0; mt < 4; mt++) {
            int row = m0 + wm * 64 + mt * 16 + g;
            float v00 = acc[mt][nt][0] + b0, v01 = acc[mt][nt][1] + b1;
            float v10 = acc[mt][nt][2] + b0, v11 = acc[mt][nt][3] + b1;
            if (MODE == 1) {
                int h = col >> 6, t = col & 63;
                float2* p0 = (float2*)&out[((size_t)h * M + row) * D_K + t];
                float2* p1 = (float2*)&out[((size_t)h * M + row + 8) * D_K + t];
                *p0 = make_float2(v00, v01);
                *p1 = make_float2(v10, v11);
            } else {
                float2* p0 = (float2*)&out[(size_t)row * N + col];
                float2* p1 = (float2*)&out[(size_t)(row + 8) * N + col];
                *p0 = make_float2(v00, v01);
                *p1 = make_float2(v10, v11);
            }
        }
    }
}

// ---------------------------------------------------------------------------
// Tensor-core flash attention (tf32 mma.sync, unnormalized-exp softmax),
// cp.async double-buffered K/V tiles.
// Grid (32, 12), 256 threads. Per CTA: 1 head, 128 q rows; kv tiles of 64.
// SMEM layout (uint32 words):
//   Qp : 128*68            (Q frags then reused as P; tf32 words)
//   Ks : 2 x 64*68         (raw f32, cvt at fragment load)
//   Vs : 2 x 64*72         (stride 72 -> conflict-free B-frag loads)
// ---------------------------------------------------------------------------
#define AST 68   // Q/P and K row stride
#define VST 72   // V row stride: bank = (8c+g)%32, bijective -> conflict-free
#define ATT_QW   (128 * AST)
#define ATT_KW   (64 * AST)
#define ATT_VW   (64 * VST)
#define ATT_SMEM_BYTES ((ATT_QW + 2 * ATT_KW + 2 * ATT_VW) * 4)

__global__ void __launch_bounds__(256) attn_tc_kernel(
    const float* __restrict__ q, const float* __restrict__ k,
    const float* __restrict__ v, float* __restrict__ out)
{
    extern __shared__ uint32_t sh[];
    uint32_t* Qp  = sh;
    uint32_t* Ksb[2] = { sh + ATT_QW, sh + ATT_QW + ATT_KW };
    uint32_t* Vsb[2] = { sh + ATT_QW + 2 * ATT_KW, sh + ATT_QW + 2 * ATT_KW + ATT_VW };

    const int tid  = threadIdx.x;
    const int wid  = tid >> 5;
    const int lane = tid & 31;
    const int g    = lane >> 2;
    const int c    = lane & 3;
    const int wr   = wid * 16;
    const int h    = blockIdx.y;
    const int q0   = blockIdx.x * 128;

    const float* kh = k + (size_t)h * N_TOK * D_K;
    const float* vh = v + (size_t)h * N_TOK * D_K;

    // Issue kv tile 0 FIRST so it overlaps the Q prologue.
    {
        uint32_t ks = smem_u32(Ksb[0]), vs = smem_u32(Vsb[0]);
#pragma unroll
        for (int i = tid; i < 1024; i += 256) {
            int r = i >> 4, c4 = (i & 15) * 4;
            CP_ASYNC16(ks + (r * AST + c4) * 4, kh + (size_t)r * D_K + c4);
            CP_ASYNC16(vs + (r * VST + c4) * 4, vh + (size_t)r * D_K + c4);
        }
        CP_COMMIT();
    }

    // Load Q tile (scaled by 0.125), convert to tf32.
    const float* qh = q + ((size_t)h * N_TOK + q0) * D_K;
#pragma unroll
    for (int i = tid; i < 2048; i += 256) {
        int r = i >> 4, c4 = (i & 15) * 4;
        float4 t = *(const float4*)(qh + (size_t)r * D_K + c4);
        uint32_t* d = &Qp[r * AST + c4];
        d[0] = f2tf32(t.x * 0.125f); d[1] = f2tf32(t.y * 0.125f);
        d[2] = f2tf32(t.z * 0.125f); d[3] = f2tf32(t.w * 0.125f);
    }
    __syncthreads();

    // Persistent Q fragments.
    uint32_t qa[8][4];
#pragma unroll
    for (int s = 0; s < 8; s++) {
        int c0 = s * 8;
        qa[s][0] = Qp[(wr + g) * AST + c0 + c];
        qa[s][1] = Qp[(wr + g + 8) * AST + c0 + c];
        qa[s][2] = Qp[(wr + g) * AST + c0 + c + 4];
        qa[s][3] = Qp[(wr + g + 8) * AST + c0 + c + 4];
    }
    __syncthreads();  // Q fully read before Qp is reused as P

    float o[8][4];
#pragma unroll
    for (int nt = 0; nt < 8; nt++)
#pragma unroll
        for (int f = 0; f < 4; f++) o[nt][f] = 0.0f;
    float ls0 = 0.0f, ls1 = 0.0f;

    const int NIT = N_TOK / 64;  // 64 iterations of 64-row kv tiles
    for (int it = 0; it < NIT; ++it) {
        const int cur = it & 1;
        if (it + 1 < NIT) {
            const int kt = (it + 1) * 64;
            uint32_t ks = smem_u32(Ksb[cur ^ 1]), vs = smem_u32(Vsb[cur ^ 1]);
#pragma unroll
            for (int i = tid; i < 1024; i += 256) {
                int r = i >> 4, c4 = (i & 15) * 4;
                CP_ASYNC16(ks + (r * AST + c4) * 4, kh + (size_t)(kt + r) * D_K + c4);
                CP_ASYNC16(vs + (r * VST + c4) * 4, vh + (size_t)(kt + r) * D_K + c4);
            }
            CP_COMMIT();
            CP_WAIT1();
        } else {
            CP_WAIT0();
        }
        __syncthreads();

        const uint32_t* Ks = Ksb[cur];
        const uint32_t* Vs = Vsb[cur];

        // S = Q.K^T (warp's 16 rows x 64 kv); exp; store P (tf32) into Qp.
#pragma unroll
        for (int nt = 0; nt < 8; nt++) {
            float sfr[4] = {0.0f, 0.0f, 0.0f, 0.0f};
#pragma unroll
            for (int s = 0; s < 8; s++) {
                uint32_t b[2];
                int n = nt * 8 + g;
                b[0] = u2tf32(Ks[n * AST + s * 8 + c]);
                b[1] = u2tf32(Ks[n * AST + s * 8 + c + 4]);
                mma_tf32(sfr, qa[s], b);
            }
            float p0 = __expf(sfr[0]), p1 = __expf(sfr[1]);
            float p2 = __expf(sfr[2]), p3 = __expf(sfr[3]);
            ls0 += p0 + p1;
            ls1 += p2 + p3;
            int col = nt * 8 + 2 * c;
            uint32_t* pp0 = &Qp[(wr + g) * AST + col];
            uint32_t* pp1 = &Qp[(wr + g + 8) * AST + col];
            pp0[0] = f2tf32(p0); pp0[1] = f2tf32(p1);
            pp1[0] = f2tf32(p2); pp1[1] = f2tf32(p3);
        }
        __syncwarp();  // P rows are warp-private

        // O += P.V
#pragma unroll
        for (int s = 0; s < 8; s++) {
            uint32_t pa[4];
            int c0 = s * 8;
            pa[0] = Qp[(wr + g) * AST + c0 + c];
            pa[1] = Qp[(wr + g + 8) * AST + c0 + c];
            pa[2] = Qp[(wr + g) * AST + c0 + c + 4];
            pa[3] = Qp[(wr + g + 8) * AST + c0 + c + 4];
#pragma unroll
            for (int nt = 0; nt < 8; nt++) {
                uint32_t b[2];
                b[0] = u2tf32(Vs[(c0 + c) * VST + nt * 8 + g]);
                b[1] = u2tf32(Vs[(c0 + c + 4) * VST + nt * 8 + g]);
                mma_tf32(o[nt], pa, b);
            }
        }
        __syncthreads();  // all reads of buf[cur] done before it+1 overwrites it
    }

    // Reduce row sums across the 4-lane quad.
    ls0 += __shfl_xor_sync(0xffffffffu, ls0, 1);
    ls0 += __shfl_xor_sync(0xffffffffu, ls0, 2);
    ls1 += __shfl_xor_sync(0xffffffffu, ls1, 1);
    ls1 += __shfl_xor_sync(0xffffffffu, ls1, 2);
    const float inv0 = 1.0f / ls0;
    const float inv1 = 1.0f / ls1;

    // Write O to [n][768] concat-head layout.
#pragma unroll
    for (int nt = 0; nt < 8; nt++) {
        int col = h * D_K + nt * 8 + 2 * c;
        float2* p0 = (float2*)&out[(size_t)(q0 + wr + g) * D_MODEL + col];
        float2* p1 = (float2*)&out[(size_t)(q0 + wr + g + 8) * D_MODEL + col];
        *p0 = make_float2(o[nt][0] * inv0, o[nt][1] * inv0);
        *p1 = make_float2(o[nt][2] * inv1, o[nt][3] * inv1);
    }
}

// ---------------------------------------------------------------------------
// Launch
// ---------------------------------------------------------------------------
extern "C" void kernel_launch(void* const* d_in, const int* in_sizes, int n_in,
                              void* d_out, int out_size)
{
    const float* Q  = (const float*)d_in[0];
    const float* K  = (const float*)d_in[1];
    const float* V  = (const float*)d_in[2];
    const float* Wq = (const float*)d_in[3];
    const float* bq = (const float*)d_in[4];
    const float* Wk = (const float*)d_in[5];
    const float* bk = (const float*)d_in[6];
    const float* Wv = (const float*)d_in[7];
    const float* bv = (const float*)d_in[8];
    const float* Wo = (const float*)d_in[9];
    const float* bo = (const float*)d_in[10];
    float* out = (float*)d_out;

    float *qb, *kb, *vb, *ab;
    cudaGetSymbolAddress((void**)&qb, g_q);
    cudaGetSymbolAddress((void**)&kb, g_k);
    cudaGetSymbolAddress((void**)&vb, g_v);
    cudaGetSymbolAddress((void**)&ab, g_attn);

    // Idempotent, capture-safe (not stream ops).
    cudaFuncSetAttribute(attn_tc_kernel,
                         cudaFuncAttributeMaxDynamicSharedMemorySize, ATT_SMEM_BYTES);
    cudaFuncSetAttribute(gemm_tc_kernel<0>,
                         cudaFuncAttributeMaxDynamicSharedMemorySize, GEMM_SMEM_BYTES);
    cudaFuncSetAttribute(gemm_tc_kernel<1>,
                         cudaFuncAttributeMaxDynamicSharedMemorySize, GEMM_SMEM_BYTES);

    dim3 gemmGrid(D_MODEL / GBN, N_TOK / GBM);  // (6, 32)

    gemm_tc_kernel<1><<<gemmGrid, 256, GEMM_SMEM_BYTES>>>(Q, Wq, bq, qb, N_TOK, D_MODEL, D_MODEL);
    gemm_tc_kernel<1><<<gemmGrid, 256, GEMM_SMEM_BYTES>>>(K, Wk, bk, kb, N_TOK, D_MODEL, D_MODEL);
    gemm_tc_kernel<1><<<gemmGrid, 256, GEMM_SMEM_BYTES>>>(V, Wv, bv, vb, N_TOK, D_MODEL, D_MODEL);

    dim3 attnGrid(N_TOK / 128, N_HEADS);        // (32, 12)
    attn_tc_kernel<<<attnGrid, 256, ATT_SMEM_BYTES>>>(qb, kb, vb, ab);

    gemm_tc_kernel<0><<<gemmGrid, 256, GEMM_SMEM_BYTES>>>(ab, Wo, bo, out, N_TOK, D_MODEL, D_MODEL);
}

// round 10
// speedup vs baseline: 4.0474x; 1.1753x over previous
#include <cuda_runtime.h>
#include <cuda_bf16.h>
#include <cstdint>

// Problem constants
#define N_TOK   4096
#define D_MODEL 768
#define N_HEADS 12
#define D_K     64
#define KV_SPLIT 2
#define SPLIT_LEN (N_TOK / KV_SPLIT)   // 2048

// ---------------------------------------------------------------------------
// Scratch buffers (all float-typed; some hold tf32-rounded bit patterns)
// ---------------------------------------------------------------------------
__device__ float g_q[N_HEADS * N_TOK * D_K];            // tf32 bits, pre-scaled 0.125
__device__ float g_k[N_HEADS * N_TOK * D_K];            // tf32 bits
__device__ float g_v[N_HEADS * N_TOK * D_K];            // tf32 bits
__device__ float g_attn[N_TOK * D_MODEL];               // tf32 bits (combine output)
__device__ float g_xc[3][N_TOK * D_MODEL];              // converted inputs Q,K,V
__device__ float g_wc[4][D_MODEL * D_MODEL];            // converted Wq,Wk,Wv,Wo
__device__ float g_op[KV_SPLIT][N_TOK * D_MODEL];       // partial O (unnormalized)
__device__ float g_lp[KV_SPLIT][N_HEADS * N_TOK];       // partial row sums

// ---------------------------------------------------------------------------
// Helpers (baseline sm_80+ PTX only)
// ---------------------------------------------------------------------------
__device__ __forceinline__ uint32_t f2tf32(float f) {
    uint32_t o;
    asm("cvt.rna.tf32.f32 %0, %1;" : "=r"(o) : "f"(f));
    return o;
}
__device__ __forceinline__ float f2tf32f(float f) {
    return __uint_as_float(f2tf32(f));
}
__device__ __forceinline__ uint32_t smem_u32(const void* p) {
    uint32_t a;
    asm("{ .reg .u64 t; cvta.to.shared.u64 t, %1; cvt.u32.u64 %0, t; }" : "=r"(a) : "l"(p));
    return a;
}
#define CP_ASYNC16(dst_u32, src) \
    asm volatile("cp.async.cg.shared.global [%0], [%1], 16;" \
                 :: "r"(dst_u32), "l"(src) : "memory")
#define CP_COMMIT() asm volatile("cp.async.commit_group;" ::: "memory")
#define CP_WAIT1()  asm volatile("cp.async.wait_group 1;" ::: "memory")
#define CP_WAIT0()  asm volatile("cp.async.wait_group 0;" ::: "memory")

// D(16x8) += A(16x8) * B(8x8); A row-major, B col-major; fp32 accum.
__device__ __forceinline__ void mma_tf32(float c[4], const uint32_t a[4],
                                         const uint32_t b[2]) {
    asm volatile(
        "mma.sync.aligned.m16n8k8.row.col.f32.tf32.tf32.f32 "
        "{%0,%1,%2,%3}, {%4,%5,%6,%7}, {%8,%9}, {%0,%1,%2,%3};"
        : "+f"(c[0]), "+f"(c[1]), "+f"(c[2]), "+f"(c[3])
        : "r"(a[0]), "r"(a[1]), "r"(a[2]), "r"(a[3]), "r"(b[0]), "r"(b[1]));
}

// ---------------------------------------------------------------------------
// Elementwise tf32 pre-conversion (RNA). n4 = element count / 4.
// ---------------------------------------------------------------------------
__global__ void cvt_tf32_kernel(const float4* __restrict__ in,
                                float4* __restrict__ out, int n4)
{
    int i = blockIdx.x * blockDim.x + threadIdx.x;
    if (i >= n4) return;
    float4 t = in[i];
    t.x = f2tf32f(t.x); t.y = f2tf32f(t.y);
    t.z = f2tf32f(t.z); t.w = f2tf32f(t.w);
    out[i] = t;
}

// ---------------------------------------------------------------------------
// GEMM mainloop constants (shared by both GEMM kernels)
// Block 128x128x32, 8 warps (2x4), warp tile 64x32. cp.async double-buffered.
// Operands are PRE-CONVERTED tf32 bits -> no cvt in the loop.
// ---------------------------------------------------------------------------
#define GBM 128
#define GBN 128
#define GBK 32
#define GST 36   // (36*g + c) % 32 = (4g+c)%32 -> conflict-free fragment loads
#define GEMM_SMEM_BYTES (2 * 2 * GBM * GST * 4)
#define GEMM_NIT (D_MODEL / GBK)   // 24

#define GEMM_PREFETCH(as_, bs_, Xp_, Wp_, k0_) \
    do { \
        for (int i_ = tid; i_ < 1024; i_ += 256) { \
            int r_ = i_ >> 3, c4_ = (i_ & 7) * 4; \
            CP_ASYNC16((as_) + (r_ * GST + c4_) * 4, (Xp_) + (size_t)r_ * D_MODEL + (k0_) + c4_); \
            CP_ASYNC16((bs_) + (r_ * GST + c4_) * 4, (Wp_) + (size_t)r_ * D_MODEL + (k0_) + c4_); \
        } \
        CP_COMMIT(); \
    } while (0)

#define GEMM_MAINLOOP(Xp_, Wp_) \
    { \
        uint32_t as0 = sbase, bs0 = sbase + GBM * GST * 4; \
        GEMM_PREFETCH(as0, bs0, Xp_, Wp_, 0); \
    } \
    for (int it = 0; it < GEMM_NIT; ++it) { \
        const int cur = it & 1; \
        if (it + 1 < GEMM_NIT) { \
            uint32_t as_ = sbase + (uint32_t)(cur ^ 1) * 2 * GBM * GST * 4; \
            uint32_t bs_ = as_ + GBM * GST * 4; \
            GEMM_PREFETCH(as_, bs_, Xp_, Wp_, (it + 1) * GBK); \
            CP_WAIT1(); \
        } else { \
            CP_WAIT0(); \
        } \
        __syncthreads(); \
        const uint32_t* As = gsh + (size_t)cur * 2 * GBM * GST; \
        const uint32_t* Bs = As + GBM * GST; \
        _Pragma("unroll") \
        for (int s = 0; s < 4; s++) { \
            const int c0 = s * 8; \
            uint32_t a[4][4], b[4][2]; \
            _Pragma("unroll") \
            for (int mt = 0; mt < 4; mt++) { \
                int r = wm * 64 + mt * 16 + g; \
                a[mt][0] = As[r * GST + c0 + c]; \
                a[mt][1] = As[(r + 8) * GST + c0 + c]; \
                a[mt][2] = As[r * GST + c0 + c + 4]; \
                a[mt][3] = As[(r + 8) * GST + c0 + c + 4]; \
            } \
            _Pragma("unroll") \
            for (int nt = 0; nt < 4; nt++) { \
                int n = wn * 32 + nt * 8 + g; \
                b[nt][0] = Bs[n * GST + c0 + c]; \
                b[nt][1] = Bs[n * GST + c0 + c + 4]; \
            } \
            _Pragma("unroll") \
            for (int mt = 0; mt < 4; mt++) \
                _Pragma("unroll") \
                for (int nt = 0; nt < 4; nt++) \
                    mma_tf32(acc[mt][nt], a[mt], b[nt]); \
        } \
        __syncthreads(); \
    }

// ---------------------------------------------------------------------------
// Fused QKV projection. Grid (6, 32, 3); z selects input/weight/bias/output.
// Output: head-split [h][m][t], tf32-rounded, q (z=0) pre-scaled by 0.125.
// ---------------------------------------------------------------------------
__global__ void __launch_bounds__(256) qkv_gemm_kernel(
    const float* __restrict__ x0, const float* __restrict__ x1, const float* __restrict__ x2,
    const float* __restrict__ w0, const float* __restrict__ w1, const float* __restrict__ w2,
    const float* __restrict__ bq_, const float* __restrict__ bk_, const float* __restrict__ bv_,
    float* __restrict__ o0, float* __restrict__ o1, float* __restrict__ o2)
{
    extern __shared__ uint32_t gsh[];
    const int tid  = threadIdx.x;
    const int wid  = tid >> 5;
    const int lane = tid & 31;
    const int g    = lane >> 2;
    const int c    = lane & 3;
    const int wm   = wid >> 2;
    const int wn   = wid & 3;
    const int m0   = blockIdx.y * GBM;
    const int n0   = blockIdx.x * GBN;
    const int z    = blockIdx.z;

    const float* X    = (z == 0) ? x0 : (z == 1) ? x1 : x2;
    const float* W    = (z == 0) ? w0 : (z == 1) ? w1 : w2;
    const float* bias = (z == 0) ? bq_ : (z == 1) ? bk_ : bv_;
    float* out        = (z == 0) ? o0 : (z == 1) ? o1 : o2;
    const float scale = (z == 0) ? 0.125f : 1.0f;

    const uint32_t sbase = smem_u32(gsh);
    const float* Xp = X + (size_t)m0 * D_MODEL;
    const float* Wp = W + (size_t)n0 * D_MODEL;

    float acc[4][4][4];
#pragma unroll
    for (int i = 0; i < 4; i++)
#pragma unroll
        for (int j = 0; j < 4; j++)
#pragma unroll
            for (int f = 0; f < 4; f++) acc[i][j][f] = 0.0f;

    GEMM_MAINLOOP(Xp, Wp)

    // Epilogue: bias, scale, tf32-round, head-split store
#pragma unroll
    for (int nt = 0; nt < 4; nt++) {
        int col = n0 + wn * 32 + nt * 8 + 2 * c;
        float b0 = bias[col], b1 = bias[col + 1];
        int h = col >> 6, t = col & 63;
#pragma unroll
        for (int mt = 0; mt < 4; mt++) {
            int row = m0 + wm * 64 + mt * 16 + g;
            float v00 = f2tf32f((acc[mt][nt][0] + b0) * scale);
            float v01 = f2tf32f((acc[mt][nt][1] + b1) * scale);
            float v10 = f2tf32f((acc[mt][nt][2] + b0) * scale);
            float v11 = f2tf32f((acc[mt][nt][3] + b1) * scale);
            *(float2*)&out[((size_t)h * N_TOK + row) * D_K + t]       = make_float2(v00, v01);
            *(float2*)&out[((size_t)h * N_TOK + row + 8) * D_K + t]   = make_float2(v10, v11);
        }
    }
}

// ---------------------------------------------------------------------------
// Output projection: out[m][o] = attn[m][k]*Wo[o][k] + bo (operands tf32 bits)
// ---------------------------------------------------------------------------
__global__ void __launch_bounds__(256) gemm_o_kernel(
    const float* __restrict__ X, const float* __restrict__ W,
    const float* __restrict__ bias, float* __restrict__ out)
{
    extern __shared__ uint32_t gsh[];
    const int tid  = threadIdx.x;
    const int wid  = tid >> 5;
    const int lane = tid & 31;
    const int g    = lane >> 2;
    const int c    = lane & 3;
    const int wm   = wid >> 2;
    const int wn   = wid & 3;
    const int m0   = blockIdx.y * GBM;
    const int n0   = blockIdx.x * GBN;

    const uint32_t sbase = smem_u32(gsh);
    const float* Xp = X + (size_t)m0 * D_MODEL;
    const float* Wp = W + (size_t)n0 * D_MODEL;

    float acc[4][4][4];
#pragma unroll
    for (int i = 0; i < 4; i++)
#pragma unroll
        for (int j = 0; j < 4; j++)
#pragma unroll
            for (int f = 0; f < 4; f++) acc[i][j][f] = 0.0f;

    GEMM_MAINLOOP(Xp, Wp)

#pragma unroll
    for (int nt = 0; nt < 4; nt++) {
        int col = n0 + wn * 32 + nt * 8 + 2 * c;
        float b0 = bias[col], b1 = bias[col + 1];
#pragma unroll
        for (int mt = 0; mt < 4; mt++) {
            int row = m0 + wm * 64 + mt * 16 + g;
            *(float2*)&out[(size_t)row * D_MODEL + col] =
                make_float2(acc[mt][nt][0] + b0, acc[mt][nt][1] + b1);
            *(float2*)&out[(size_t)(row + 8) * D_MODEL + col] =
                make_float2(acc[mt][nt][2] + b0, acc[mt][nt][3] + b1);
        }
    }
}

// ---------------------------------------------------------------------------
// Flash attention, split-KV. Grid (32, 12, 2), 256 threads.
// q/k/v hold tf32 bits (q pre-scaled). Per CTA: 1 head, 128 q rows,
// kv range [sp*2048, (sp+1)*2048), 32 double-buffered 64-row tiles.
// Writes unnormalized partial O and row sums l.
// ---------------------------------------------------------------------------
#define AST 68   // Q/P and K row stride
#define VST 72   // V row stride: bank = (8c+g)%32 over warp -> conflict-free
#define ATT_QW   (128 * AST)
#define ATT_KW   (64 * AST)
#define ATT_VW   (64 * VST)
#define ATT_SMEM_BYTES ((ATT_QW + 2 * ATT_KW + 2 * ATT_VW) * 4)

__global__ void __launch_bounds__(256) attn_tc_kernel(
    const float* __restrict__ q, const float* __restrict__ k,
    const float* __restrict__ v, float* __restrict__ opart,
    float* __restrict__ lpart)
{
    extern __shared__ uint32_t sh[];
    uint32_t* Qp  = sh;
    uint32_t* Ksb[2] = { sh + ATT_QW, sh + ATT_QW + ATT_KW };
    uint32_t* Vsb[2] = { sh + ATT_QW + 2 * ATT_KW, sh + ATT_QW + 2 * ATT_KW + ATT_VW };

    const int tid  = threadIdx.x;
    const int wid  = tid >> 5;
    const int lane = tid & 31;
    const int g    = lane >> 2;
    const int c    = lane & 3;
    const int wr   = wid * 16;
    const int h    = blockIdx.y;
    const int q0   = blockIdx.x * 128;
    const int sp   = blockIdx.z;

    float* op = opart + (size_t)sp * N_TOK * D_MODEL;
    float* lp = lpart + (size_t)sp * N_HEADS * N_TOK;

    const float* kh = k + ((size_t)h * N_TOK + sp * SPLIT_LEN) * D_K;
    const float* vh = v + ((size_t)h * N_TOK + sp * SPLIT_LEN) * D_K;

    // Prefetch kv tile 0 (overlaps Q prologue).
    {
        uint32_t ks = smem_u32(Ksb[0]), vs = smem_u32(Vsb[0]);
#pragma unroll
        for (int i = tid; i < 1024; i += 256) {
            int r = i >> 4, c4 = (i & 15) * 4;
            CP_ASYNC16(ks + (r * AST + c4) * 4, kh + (size_t)r * D_K + c4);
            CP_ASYNC16(vs + (r * VST + c4) * 4, vh + (size_t)r * D_K + c4);
        }
        CP_COMMIT();
    }

    // Q tile: already scaled + tf32 bits -> plain copy.
    const float* qh = q + ((size_t)h * N_TOK + q0) * D_K;
#pragma unroll
    for (int i = tid; i < 2048; i += 256) {
        int r = i >> 4, c4 = (i & 15) * 4;
        uint4 t = *(const uint4*)(qh + (size_t)r * D_K + c4);
        *(uint4*)&Qp[r * AST + c4] = t;
    }
    __syncthreads();

    // Persistent Q fragments.
    uint32_t qa[8][4];
#pragma unroll
    for (int s = 0; s < 8; s++) {
        int c0 = s * 8;
        qa[s][0] = Qp[(wr + g) * AST + c0 + c];
        qa[s][1] = Qp[(wr + g + 8) * AST + c0 + c];
        qa[s][2] = Qp[(wr + g) * AST + c0 + c + 4];
        qa[s][3] = Qp[(wr + g + 8) * AST + c0 + c + 4];
    }
    __syncthreads();  // Q fully read before Qp is reused as P

    float o[8][4];
#pragma unroll
    for (int nt = 0; nt < 8; nt++)
#pragma unroll
        for (int f = 0; f < 4; f++) o[nt][f] = 0.0f;
    float ls0 = 0.0f, ls1 = 0.0f;

    const int NIT = SPLIT_LEN / 64;  // 32
    for (int it = 0; it < NIT; ++it) {
        const int cur = it & 1;
        if (it + 1 < NIT) {
            const int kt = (it + 1) * 64;
            uint32_t ks = smem_u32(Ksb[cur ^ 1]), vs = smem_u32(Vsb[cur ^ 1]);
#pragma unroll
            for (int i = tid; i < 1024; i += 256) {
                int r = i >> 4, c4 = (i & 15) * 4;
                CP_ASYNC16(ks + (r * AST + c4) * 4, kh + (size_t)(kt + r) * D_K + c4);
                CP_ASYNC16(vs + (r * VST + c4) * 4, vh + (size_t)(kt + r) * D_K + c4);
            }
            CP_COMMIT();
            CP_WAIT1();
        } else {
            CP_WAIT0();
        }
        __syncthreads();

        const uint32_t* Ks = Ksb[cur];
        const uint32_t* Vs = Vsb[cur];

        // S = Q.K^T (warp's 16 rows x 64 kv); exp; store P (tf32) into Qp.
#pragma unroll
        for (int nt = 0; nt < 8; nt++) {
            float sfr[4] = {0.0f, 0.0f, 0.0f, 0.0f};
#pragma unroll
            for (int s = 0; s < 8; s++) {
                uint32_t b[2];
                int n = nt * 8 + g;
                b[0] = Ks[n * AST + s * 8 + c];
                b[1] = Ks[n * AST + s * 8 + c + 4];
                mma_tf32(sfr, qa[s], b);
            }
            float p0 = __expf(sfr[0]), p1 = __expf(sfr[1]);
            float p2 = __expf(sfr[2]), p3 = __expf(sfr[3]);
            ls0 += p0 + p1;
            ls1 += p2 + p3;
            int col = nt * 8 + 2 * c;
            uint32_t* pp0 = &Qp[(wr + g) * AST + col];
            uint32_t* pp1 = &Qp[(wr + g + 8) * AST + col];
            pp0[0] = f2tf32(p0); pp0[1] = f2tf32(p1);
            pp1[0] = f2tf32(p2); pp1[1] = f2tf32(p3);
        }
        __syncwarp();  // P rows are warp-private

        // O += P.V
#pragma unroll
        for (int s = 0; s < 8; s++) {
            uint32_t pa[4];
            int c0 = s * 8;
            pa[0] = Qp[(wr + g) * AST + c0 + c];
            pa[1] = Qp[(wr + g + 8) * AST + c0 + c];
            pa[2] = Qp[(wr + g) * AST + c0 + c + 4];
            pa[3] = Qp[(wr + g + 8) * AST + c0 + c + 4];
#pragma unroll
            for (int nt = 0; nt < 8; nt++) {
                uint32_t b[2];
                b[0] = Vs[(c0 + c) * VST + nt * 8 + g];
                b[1] = Vs[(c0 + c + 4) * VST + nt * 8 + g];
                mma_tf32(o[nt], pa, b);
            }
        }
        __syncthreads();  // all reads of buf[cur] done before next prefetch
    }

    // Row sums across the 4-lane quad.
    ls0 += __shfl_xor_sync(0xffffffffu, ls0, 1);
    ls0 += __shfl_xor_sync(0xffffffffu, ls0, 2);
    ls1 += __shfl_xor_sync(0xffffffffu, ls1, 1);
    ls1 += __shfl_xor_sync(0xffffffffu, ls1, 2);
    if (c == 0) {
        lp[(size_t)h * N_TOK + q0 + wr + g]     = ls0;
        lp[(size_t)h * N_TOK + q0 + wr + g + 8] = ls1;
    }

    // Write unnormalized partial O ([n][768] concat-head layout).
#pragma unroll
    for (int nt = 0; nt < 8; nt++) {
        int col = h * D_K + nt * 8 + 2 * c;
        *(float2*)&op[(size_t)(q0 + wr + g) * D_MODEL + col] =
            make_float2(o[nt][0], o[nt][1]);
        *(float2*)&op[(size_t)(q0 + wr + g + 8) * D_MODEL + col] =
            make_float2(o[nt][2], o[nt][3]);
    }
}

// ---------------------------------------------------------------------------
// Combine: attn[r][c] = tf32((O0+O1)/(l0+l1))
// ---------------------------------------------------------------------------
__global__ void combine_kernel(const float* __restrict__ opart,
                               const float* __restrict__ lpart,
                               float* __restrict__ out)
{
    int i = blockIdx.x * blockDim.x + threadIdx.x;   // float4 index
    if (i >= N_TOK * D_MODEL / 4) return;
    int r  = i / (D_MODEL / 4);
    int c4 = (i % (D_MODEL / 4)) * 4;
    int h  = c4 >> 6;
    float l = lpart[(size_t)h * N_TOK + r] +
              lpart[(size_t)N_HEADS * N_TOK + (size_t)h * N_TOK + r];
    float inv = 1.0f / l;
    float4 a = ((const float4*)opart)[i];
    float4 b = ((const float4*)(opart + (size_t)N_TOK * D_MODEL))[i];
    float4 o;
    o.x = f2tf32f((a.x + b.x) * inv);
    o.y = f2tf32f((a.y + b.y) * inv);
    o.z = f2tf32f((a.z + b.z) * inv);
    o.w = f2tf32f((a.w + b.w) * inv);
    ((float4*)out)[i] = o;
}

// ---------------------------------------------------------------------------
// Launch
// ---------------------------------------------------------------------------
extern "C" void kernel_launch(void* const* d_in, const int* in_sizes, int n_in,
                              void* d_out, int out_size)
{
    const float* Q  = (const float*)d_in[0];
    const float* K  = (const float*)d_in[1];
    const float* V  = (const float*)d_in[2];
    const float* Wq = (const float*)d_in[3];
    const float* bq = (const float*)d_in[4];
    const float* Wk = (const float*)d_in[5];
    const float* bk = (const float*)d_in[6];
    const float* Wv = (const float*)d_in[7];
    const float* bv = (const float*)d_in[8];
    const float* Wo = (const float*)d_in[9];
    const float* bo = (const float*)d_in[10];
    float* out = (float*)d_out;

    float *qb, *kb, *vb, *ab, *xc, *wc, *op, *lp;
    cudaGetSymbolAddress((void**)&qb, g_q);
    cudaGetSymbolAddress((void**)&kb, g_k);
    cudaGetSymbolAddress((void**)&vb, g_v);
    cudaGetSymbolAddress((void**)&ab, g_attn);
    cudaGetSymbolAddress((void**)&xc, g_xc);
    cudaGetSymbolAddress((void**)&wc, g_wc);
    cudaGetSymbolAddress((void**)&op, g_op);
    cudaGetSymbolAddress((void**)&lp, g_lp);

    float* xc0 = xc;
    float* xc1 = xc + (size_t)N_TOK * D_MODEL;
    float* xc2 = xc + 2 * (size_t)N_TOK * D_MODEL;
    float* wc0 = wc;
    float* wc1 = wc + (size_t)D_MODEL * D_MODEL;
    float* wc2 = wc + 2 * (size_t)D_MODEL * D_MODEL;
    float* wc3 = wc + 3 * (size_t)D_MODEL * D_MODEL;

    // Idempotent, capture-safe (not stream ops).
    cudaFuncSetAttribute(attn_tc_kernel,
                         cudaFuncAttributeMaxDynamicSharedMemorySize, ATT_SMEM_BYTES);
    cudaFuncSetAttribute(qkv_gemm_kernel,
                         cudaFuncAttributeMaxDynamicSharedMemorySize, GEMM_SMEM_BYTES);
    cudaFuncSetAttribute(gemm_o_kernel,
                         cudaFuncAttributeMaxDynamicSharedMemorySize, GEMM_SMEM_BYTES);

    // 1) Pre-convert operands to tf32 (RNA).
    const int NX4 = N_TOK * D_MODEL / 4;      // 786432
    const int NW4 = D_MODEL * D_MODEL / 4;    // 147456
    cvt_tf32_kernel<<<(NX4 + 255) / 256, 256>>>((const float4*)Q, (float4*)xc0, NX4);
    cvt_tf32_kernel<<<(NX4 + 255) / 256, 256>>>((const float4*)K, (float4*)xc1, NX4);
    cvt_tf32_kernel<<<(NX4 + 255) / 256, 256>>>((const float4*)V, (float4*)xc2, NX4);
    cvt_tf32_kernel<<<(NW4 + 255) / 256, 256>>>((const float4*)Wq, (float4*)wc0, NW4);
    cvt_tf32_kernel<<<(NW4 + 255) / 256, 256>>>((const float4*)Wk, (float4*)wc1, NW4);
    cvt_tf32_kernel<<<(NW4 + 255) / 256, 256>>>((const float4*)Wv, (float4*)wc2, NW4);
    cvt_tf32_kernel<<<(NW4 + 255) / 256, 256>>>((const float4*)Wo, (float4*)wc3, NW4);

    // 2) Fused QKV projections.
    dim3 qkvGrid(D_MODEL / GBN, N_TOK / GBM, 3);   // (6, 32, 3)
    qkv_gemm_kernel<<<qkvGrid, 256, GEMM_SMEM_BYTES>>>(
        xc0, xc1, xc2, wc0, wc1, wc2, bq, bk, bv, qb, kb, vb);

    // 3) Split-KV attention.
    dim3 attnGrid(N_TOK / 128, N_HEADS, KV_SPLIT); // (32, 12, 2)
    attn_tc_kernel<<<attnGrid, 256, ATT_SMEM_BYTES>>>(qb, kb, vb, op, lp);

    // 4) Combine partials -> g_attn (tf32 bits).
    combine_kernel<<<(NX4 + 255) / 256, 256>>>(op, lp, ab);

    // 5) Output projection.
    dim3 oGrid(D_MODEL / GBN, N_TOK / GBM);        // (6, 32)
    gemm_o_kernel<<<oGrid, 256, GEMM_SMEM_BYTES>>>(ab, wc3, bo, out);
}

// round 11
// speedup vs baseline: 5.2155x; 1.2886x over previous
#include <cuda_runtime.h>
#include <cstdint>

// Problem constants
#define N_TOK   4096
#define D_MODEL 768
#define N_HEADS 12
#define D_K     64
#define KV_SPLIT 4
#define SPLIT_LEN (N_TOK / KV_SPLIT)   // 1024

// ---------------------------------------------------------------------------
// Scratch buffers (float-typed; several hold tf32-rounded bit patterns)
// ---------------------------------------------------------------------------
__device__ float g_q[N_HEADS * N_TOK * D_K];            // tf32 bits, pre-scaled 0.125
__device__ float g_k[N_HEADS * N_TOK * D_K];            // tf32 bits, [h][tok][dk]
__device__ float g_v[N_HEADS * D_K * N_TOK];            // tf32 bits, TRANSPOSED [h][dk][tok]
__device__ float g_attn[N_TOK * D_MODEL];               // tf32 bits (combine output)
__device__ float g_xc[3][N_TOK * D_MODEL];              // converted inputs Q,K,V
__device__ float g_wc[4][D_MODEL * D_MODEL];            // converted Wq,Wk,Wv,Wo
__device__ float g_op[KV_SPLIT][N_TOK * D_MODEL];       // partial O (unnormalized)
__device__ float g_lp[KV_SPLIT][N_HEADS * N_TOK];       // partial row sums

// ---------------------------------------------------------------------------
// Helpers (baseline sm_80+ PTX only)
// ---------------------------------------------------------------------------
__device__ __forceinline__ uint32_t f2tf32(float f) {
    uint32_t o;
    asm("cvt.rna.tf32.f32 %0, %1;" : "=r"(o) : "f"(f));
    return o;
}
__device__ __forceinline__ float f2tf32f(float f) {
    return __uint_as_float(f2tf32(f));
}
__device__ __forceinline__ uint32_t smem_u32(const void* p) {
    uint32_t a;
    asm("{ .reg .u64 t; cvta.to.shared.u64 t, %1; cvt.u32.u64 %0, t; }" : "=r"(a) : "l"(p));
    return a;
}
#define CP_ASYNC16(dst_u32, src) \
    asm volatile("cp.async.cg.shared.global [%0], [%1], 16;" \
                 :: "r"(dst_u32), "l"(src) : "memory")
#define CP_COMMIT() asm volatile("cp.async.commit_group;" ::: "memory")
#define CP_WAIT1()  asm volatile("cp.async.wait_group 1;" ::: "memory")
#define CP_WAIT0()  asm volatile("cp.async.wait_group 0;" ::: "memory")

__device__ __forceinline__ void ldsm_x4(uint32_t& r0, uint32_t& r1,
                                        uint32_t& r2, uint32_t& r3, uint32_t addr) {
    asm volatile("ldmatrix.sync.aligned.m8n8.x4.shared.b16 {%0,%1,%2,%3}, [%4];"
                 : "=r"(r0), "=r"(r1), "=r"(r2), "=r"(r3) : "r"(addr));
}

// D(16x8) += A(16x8) * B(8x8); A row-major, B col-major; fp32 accum.
__device__ __forceinline__ void mma_tf32(float c[4], const uint32_t a[4],
                                         const uint32_t b[2]) {
    asm volatile(
        "mma.sync.aligned.m16n8k8.row.col.f32.tf32.tf32.f32 "
        "{%0,%1,%2,%3}, {%4,%5,%6,%7}, {%8,%9}, {%0,%1,%2,%3};"
        : "+f"(c[0]), "+f"(c[1]), "+f"(c[2]), "+f"(c[3])
        : "r"(a[0]), "r"(a[1]), "r"(a[2]), "r"(a[3]), "r"(b[0]), "r"(b[1]));
}

// ---------------------------------------------------------------------------
// Fused tf32 pre-conversion: inputs (y=0..2) and weights (y=0..3)
// ---------------------------------------------------------------------------
#define NX4 (N_TOK * D_MODEL / 4)
#define NW4 (D_MODEL * D_MODEL / 4)

__global__ void cvt_inputs_kernel(const float4* __restrict__ a,
                                  const float4* __restrict__ b,
                                  const float4* __restrict__ cc,
                                  float4* __restrict__ dst)
{
    int i = blockIdx.x * blockDim.x + threadIdx.x;
    if (i >= NX4) return;
    const float4* src = (blockIdx.y == 0) ? a : (blockIdx.y == 1) ? b : cc;
    float4 t = src[i];
    t.x = f2tf32f(t.x); t.y = f2tf32f(t.y);
    t.z = f2tf32f(t.z); t.w = f2tf32f(t.w);
    dst[(size_t)blockIdx.y * NX4 + i] = t;
}
__global__ void cvt_weights_kernel(const float4* __restrict__ a,
                                   const float4* __restrict__ b,
                                   const float4* __restrict__ cc,
                                   const float4* __restrict__ d,
                                   float4* __restrict__ dst)
{
    int i = blockIdx.x * blockDim.x + threadIdx.x;
    if (i >= NW4) return;
    const float4* src = (blockIdx.y == 0) ? a : (blockIdx.y == 1) ? b
                      : (blockIdx.y == 2) ? cc : d;
    float4 t = src[i];
    t.x = f2tf32f(t.x); t.y = f2tf32f(t.y);
    t.z = f2tf32f(t.z); t.w = f2tf32f(t.w);
    dst[(size_t)blockIdx.y * NW4 + i] = t;
}

// ---------------------------------------------------------------------------
// GEMM mainloop (shared): block 128x128x32, 8 warps (2x4), warp tile 64x32,
// cp.async double-buffered, operands pre-converted tf32 bits (no cvt in loop).
// ---------------------------------------------------------------------------
#define GBM 128
#define GBN 128
#define GBK 32
#define GST 36
#define GEMM_SMEM_BYTES (2 * 2 * GBM * GST * 4)
#define GEMM_NIT (D_MODEL / GBK)   // 24

#define GEMM_PREFETCH(as_, bs_, Xp_, Wp_, k0_) \
    do { \
        for (int i_ = tid; i_ < 1024; i_ += 256) { \
            int r_ = i_ >> 3, c4_ = (i_ & 7) * 4; \
            CP_ASYNC16((as_) + (r_ * GST + c4_) * 4, (Xp_) + (size_t)r_ * D_MODEL + (k0_) + c4_); \
            CP_ASYNC16((bs_) + (r_ * GST + c4_) * 4, (Wp_) + (size_t)r_ * D_MODEL + (k0_) + c4_); \
        } \
        CP_COMMIT(); \
    } while (0)

#define GEMM_MAINLOOP(Xp_, Wp_) \
    { \
        uint32_t as0 = sbase, bs0 = sbase + GBM * GST * 4; \
        GEMM_PREFETCH(as0, bs0, Xp_, Wp_, 0); \
    } \
    for (int it = 0; it < GEMM_NIT; ++it) { \
        const int cur = it & 1; \
        if (it + 1 < GEMM_NIT) { \
            uint32_t as_ = sbase + (uint32_t)(cur ^ 1) * 2 * GBM * GST * 4; \
            uint32_t bs_ = as_ + GBM * GST * 4; \
            GEMM_PREFETCH(as_, bs_, Xp_, Wp_, (it + 1) * GBK); \
            CP_WAIT1(); \
        } else { \
            CP_WAIT0(); \
        } \
        __syncthreads(); \
        const uint32_t* As = gsh + (size_t)cur * 2 * GBM * GST; \
        const uint32_t* Bs = As + GBM * GST; \
        _Pragma("unroll") \
        for (int s = 0; s < 4; s++) { \
            const int c0 = s * 8; \
            uint32_t a[4][4], b[4][2]; \
            _Pragma("unroll") \
            for (int mt = 0; mt < 4; mt++) { \
                int r = wm * 64 + mt * 16 + g; \
                a[mt][0] = As[r * GST + c0 + c]; \
                a[mt][1] = As[(r + 8) * GST + c0 + c]; \
                a[mt][2] = As[r * GST + c0 + c + 4]; \
                a[mt][3] = As[(r + 8) * GST + c0 + c + 4]; \
            } \
            _Pragma("unroll") \
            for (int nt = 0; nt < 4; nt++) { \
                int n = wn * 32 + nt * 8 + g; \
                b[nt][0] = Bs[n * GST + c0 + c]; \
                b[nt][1] = Bs[n * GST + c0 + c + 4]; \
            } \
            _Pragma("unroll") \
            for (int mt = 0; mt < 4; mt++) \
                _Pragma("unroll") \
                for (int nt = 0; nt < 4; nt++) \
                    mma_tf32(acc[mt][nt], a[mt], b[nt]); \
        } \
        __syncthreads(); \
    }

// ---------------------------------------------------------------------------
// Fused QKV projection. Grid (6, 32, 3). z=0: q (scaled, [h][tok][dk]),
// z=1: k ([h][tok][dk]), z=2: v TRANSPOSED ([h][dk][tok]). tf32-rounded.
// ---------------------------------------------------------------------------
__global__ void __launch_bounds__(256) qkv_gemm_kernel(
    const float* __restrict__ x0, const float* __restrict__ x1, const float* __restrict__ x2,
    const float* __restrict__ w0, const float* __restrict__ w1, const float* __restrict__ w2,
    const float* __restrict__ bq_, const float* __restrict__ bk_, const float* __restrict__ bv_,
    float* __restrict__ o0, float* __restrict__ o1, float* __restrict__ o2)
{
    extern __shared__ uint32_t gsh[];
    const int tid  = threadIdx.x;
    const int wid  = tid >> 5;
    const int lane = tid & 31;
    const int g    = lane >> 2;
    const int c    = lane & 3;
    const int wm   = wid >> 2;
    const int wn   = wid & 3;
    const int m0   = blockIdx.y * GBM;
    const int n0   = blockIdx.x * GBN;
    const int z    = blockIdx.z;

    const float* X    = (z == 0) ? x0 : (z == 1) ? x1 : x2;
    const float* W    = (z == 0) ? w0 : (z == 1) ? w1 : w2;
    const float* bias = (z == 0) ? bq_ : (z == 1) ? bk_ : bv_;
    const float scale = (z == 0) ? 0.125f : 1.0f;

    const uint32_t sbase = smem_u32(gsh);
    const float* Xp = X + (size_t)m0 * D_MODEL;
    const float* Wp = W + (size_t)n0 * D_MODEL;

    float acc[4][4][4];
#pragma unroll
    for (int i = 0; i < 4; i++)
#pragma unroll
        for (int j = 0; j < 4; j++)
#pragma unroll
            for (int f = 0; f < 4; f++) acc[i][j][f] = 0.0f;

    GEMM_MAINLOOP(Xp, Wp)

#pragma unroll
    for (int nt = 0; nt < 4; nt++) {
        int col = n0 + wn * 32 + nt * 8 + 2 * c;
        float b0 = bias[col], b1 = bias[col + 1];
        int h = col >> 6, t = col & 63;
#pragma unroll
        for (int mt = 0; mt < 4; mt++) {
            int row = m0 + wm * 64 + mt * 16 + g;
            float v00 = f2tf32f((acc[mt][nt][0] + b0) * scale);
            float v01 = f2tf32f((acc[mt][nt][1] + b1) * scale);
            float v10 = f2tf32f((acc[mt][nt][2] + b0) * scale);
            float v11 = f2tf32f((acc[mt][nt][3] + b1) * scale);
            if (z == 2) {
                // transposed: [h][dk][tok]
                float* vp = o2;
                vp[((size_t)h * D_K + t)     * N_TOK + row]     = v00;
                vp[((size_t)h * D_K + t + 1) * N_TOK + row]     = v01;
                vp[((size_t)h * D_K + t)     * N_TOK + row + 8] = v10;
                vp[((size_t)h * D_K + t + 1) * N_TOK + row + 8] = v11;
            } else {
                float* outp = (z == 0) ? o0 : o1;
                *(float2*)&outp[((size_t)h * N_TOK + row) * D_K + t]     = make_float2(v00, v01);
                *(float2*)&outp[((size_t)h * N_TOK + row + 8) * D_K + t] = make_float2(v10, v11);
            }
        }
    }
}

// ---------------------------------------------------------------------------
// Output projection
// ---------------------------------------------------------------------------
__global__ void __launch_bounds__(256) gemm_o_kernel(
    const float* __restrict__ X, const float* __restrict__ W,
    const float* __restrict__ bias, float* __restrict__ out)
{
    extern __shared__ uint32_t gsh[];
    const int tid  = threadIdx.x;
    const int wid  = tid >> 5;
    const int lane = tid & 31;
    const int g    = lane >> 2;
    const int c    = lane & 3;
    const int wm   = wid >> 2;
    const int wn   = wid & 3;
    const int m0   = blockIdx.y * GBM;
    const int n0   = blockIdx.x * GBN;

    const uint32_t sbase = smem_u32(gsh);
    const float* Xp = X + (size_t)m0 * D_MODEL;
    const float* Wp = W + (size_t)n0 * D_MODEL;

    float acc[4][4][4];
#pragma unroll
    for (int i = 0; i < 4; i++)
#pragma unroll
        for (int j = 0; j < 4; j++)
#pragma unroll
            for (int f = 0; f < 4; f++) acc[i][j][f] = 0.0f;

    GEMM_MAINLOOP(Xp, Wp)

#pragma unroll
    for (int nt = 0; nt < 4; nt++) {
        int col = n0 + wn * 32 + nt * 8 + 2 * c;
        float b0 = bias[col], b1 = bias[col + 1];
#pragma unroll
        for (int mt = 0; mt < 4; mt++) {
            int row = m0 + wm * 64 + mt * 16 + g;
            *(float2*)&out[(size_t)row * D_MODEL + col] =
                make_float2(acc[mt][nt][0] + b0, acc[mt][nt][1] + b1);
            *(float2*)&out[(size_t)(row + 8) * D_MODEL + col] =
                make_float2(acc[mt][nt][2] + b0, acc[mt][nt][3] + b1);
        }
    }
}

// ---------------------------------------------------------------------------
// Flash attention, split-KV, ldmatrix fragment loads.
// Grid (32, 12, KV_SPLIT), 256 threads. kv tiles of 64, double-buffered.
// smem: Qp[128*68] (Q then P), Ks 2x[64*68] ([kv][dk]), Vt 2x[64*68] ([dk][kv]).
// ---------------------------------------------------------------------------
#define AST 68
#define VST2 68
#define ATT_QW   (128 * AST)
#define ATT_KW   (64 * AST)
#define ATT_VW   (64 * VST2)
#define ATT_SMEM_BYTES ((ATT_QW + 2 * ATT_KW + 2 * ATT_VW) * 4)

__global__ void __launch_bounds__(256) attn_tc_kernel(
    const float* __restrict__ q, const float* __restrict__ k,
    const float* __restrict__ v, float* __restrict__ opart,
    float* __restrict__ lpart)
{
    extern __shared__ uint32_t sh[];
    uint32_t* Qp  = sh;
    uint32_t* Ksb[2] = { sh + ATT_QW, sh + ATT_QW + ATT_KW };
    uint32_t* Vsb[2] = { sh + ATT_QW + 2 * ATT_KW, sh + ATT_QW + 2 * ATT_KW + ATT_VW };

    const int tid  = threadIdx.x;
    const int wid  = tid >> 5;
    const int lane = tid & 31;
    const int g    = lane >> 2;
    const int c    = lane & 3;
    const int wr   = wid * 16;
    const int h    = blockIdx.y;
    const int q0   = blockIdx.x * 128;
    const int sp   = blockIdx.z;

    float* op = opart + (size_t)sp * N_TOK * D_MODEL;
    float* lp = lpart + (size_t)sp * N_HEADS * N_TOK;

    const float* kh = k + ((size_t)h * N_TOK + sp * SPLIT_LEN) * D_K;   // [tok][dk]
    const float* vh = v + (size_t)h * D_K * N_TOK + sp * SPLIT_LEN;     // [dk][tok]

    // ldmatrix per-lane address components (bytes)
    const int m_ = lane >> 3, r_ = lane & 7;
    const uint32_t QpA = smem_u32(Qp);
    const uint32_t KsA0 = smem_u32(Ksb[0]), KsA1 = smem_u32(Ksb[1]);
    const uint32_t VsA0 = smem_u32(Vsb[0]), VsA1 = smem_u32(Vsb[1]);
    // K B-frag: matrix m -> kw = 4j+m, row = nt*8 + r
    const uint32_t kOff = (uint32_t)(r_ * AST + 4 * m_) * 4;
    // P A-frag: matrix m -> row = wr + (m&1)*8 + r, wcol = s*8 + (m>>1)*4
    const uint32_t pOff = (uint32_t)((wr + (m_ & 1) * 8 + r_) * AST + (m_ >> 1) * 4) * 4;
    // V B-frag: matrix m -> row dk = (2j + (m>>1))*8 + r, wcol = s*8 + (m&1)*4
    const uint32_t vOff = (uint32_t)(((m_ >> 1) * 8 + r_) * VST2 + 4 * (m_ & 1)) * 4;

    // Prefetch kv tile 0.
    {
        uint32_t ks = KsA0, vs = VsA0;
#pragma unroll
        for (int i = tid; i < 1024; i += 256) {
            int r = i >> 4, c4 = (i & 15) * 4;
            CP_ASYNC16(ks + (r * AST + c4) * 4, kh + (size_t)r * D_K + c4);
            CP_ASYNC16(vs + (r * VST2 + c4) * 4, vh + (size_t)r * N_TOK + c4);
        }
        CP_COMMIT();
    }

    // Q tile: already scaled + tf32 bits -> plain copy.
    const float* qh = q + ((size_t)h * N_TOK + q0) * D_K;
#pragma unroll
    for (int i = tid; i < 2048; i += 256) {
        int r = i >> 4, c4 = (i & 15) * 4;
        uint4 t = *(const uint4*)(qh + (size_t)r * D_K + c4);
        *(uint4*)&Qp[r * AST + c4] = t;
    }
    __syncthreads();

    // Persistent Q fragments.
    uint32_t qa[8][4];
#pragma unroll
    for (int s = 0; s < 8; s++) {
        int c0 = s * 8;
        qa[s][0] = Qp[(wr + g) * AST + c0 + c];
        qa[s][1] = Qp[(wr + g + 8) * AST + c0 + c];
        qa[s][2] = Qp[(wr + g) * AST + c0 + c + 4];
        qa[s][3] = Qp[(wr + g + 8) * AST + c0 + c + 4];
    }
    __syncthreads();  // Q fully read before Qp is reused as P

    float o[8][4];
#pragma unroll
    for (int nt = 0; nt < 8; nt++)
#pragma unroll
        for (int f = 0; f < 4; f++) o[nt][f] = 0.0f;
    float ls0 = 0.0f, ls1 = 0.0f;

    const int NIT = SPLIT_LEN / 64;  // 16
    for (int it = 0; it < NIT; ++it) {
        const int cur = it & 1;
        if (it + 1 < NIT) {
            const int kt = (it + 1) * 64;
            uint32_t ks = cur ? KsA0 : KsA1;
            uint32_t vs = cur ? VsA0 : VsA1;
#pragma unroll
            for (int i = tid; i < 1024; i += 256) {
                int r = i >> 4, c4 = (i & 15) * 4;
                CP_ASYNC16(ks + (r * AST + c4) * 4, kh + (size_t)(kt + r) * D_K + c4);
                CP_ASYNC16(vs + (r * VST2 + c4) * 4, vh + (size_t)r * N_TOK + kt + c4);
            }
            CP_COMMIT();
            CP_WAIT1();
        } else {
            CP_WAIT0();
        }
        __syncthreads();

        const uint32_t KsA = cur ? KsA1 : KsA0;
        const uint32_t VsA = cur ? VsA1 : VsA0;

        // S = Q.K^T; exp; store P (tf32) into Qp.
#pragma unroll
        for (int nt = 0; nt < 8; nt++) {
            uint32_t bb[8][2];
            const uint32_t kb = KsA + kOff + (uint32_t)nt * (8 * AST * 4);
#pragma unroll
            for (int j = 0; j < 4; j++)
                ldsm_x4(bb[2 * j][0], bb[2 * j][1], bb[2 * j + 1][0], bb[2 * j + 1][1],
                        kb + (uint32_t)j * 64);
            float sfr[4] = {0.0f, 0.0f, 0.0f, 0.0f};
#pragma unroll
            for (int s = 0; s < 8; s++)
                mma_tf32(sfr, qa[s], bb[s]);

            float p0 = __expf(sfr[0]), p1 = __expf(sfr[1]);
            float p2 = __expf(sfr[2]), p3 = __expf(sfr[3]);
            ls0 += p0 + p1;
            ls1 += p2 + p3;
            int col = nt * 8 + 2 * c;
            *(uint2*)&Qp[(wr + g) * AST + col]     = make_uint2(f2tf32(p0), f2tf32(p1));
            *(uint2*)&Qp[(wr + g + 8) * AST + col] = make_uint2(f2tf32(p2), f2tf32(p3));
        }
        __syncwarp();  // P rows are warp-private

        // O += P.V   (A = P via ldmatrix, B = Vt via ldmatrix)
#pragma unroll
        for (int s = 0; s < 8; s++) {
            uint32_t pa[4];
            ldsm_x4(pa[0], pa[1], pa[2], pa[3], QpA + pOff + (uint32_t)s * 32);
            const uint32_t vb = VsA + vOff + (uint32_t)s * 32;
#pragma unroll
            for (int j = 0; j < 4; j++) {
                uint32_t b0, b1, b2, b3;
                ldsm_x4(b0, b1, b2, b3, vb + (uint32_t)j * (16 * VST2 * 4));
                uint32_t bA[2] = {b0, b1}, bB[2] = {b2, b3};
                mma_tf32(o[2 * j], pa, bA);
                mma_tf32(o[2 * j + 1], pa, bB);
            }
        }
        __syncthreads();  // all reads of buf[cur] done before next prefetch
    }

    // Row sums across the 4-lane quad.
    ls0 += __shfl_xor_sync(0xffffffffu, ls0, 1);
    ls0 += __shfl_xor_sync(0xffffffffu, ls0, 2);
    ls1 += __shfl_xor_sync(0xffffffffu, ls1, 1);
    ls1 += __shfl_xor_sync(0xffffffffu, ls1, 2);
    if (c == 0) {
        lp[(size_t)h * N_TOK + q0 + wr + g]     = ls0;
        lp[(size_t)h * N_TOK + q0 + wr + g + 8] = ls1;
    }

    // Write unnormalized partial O ([n][768] concat-head layout).
#pragma unroll
    for (int nt = 0; nt < 8; nt++) {
        int col = h * D_K + nt * 8 + 2 * c;
        *(float2*)&op[(size_t)(q0 + wr + g) * D_MODEL + col] =
            make_float2(o[nt][0], o[nt][1]);
        *(float2*)&op[(size_t)(q0 + wr + g + 8) * D_MODEL + col] =
            make_float2(o[nt][2], o[nt][3]);
    }
}

// ---------------------------------------------------------------------------
// Combine: attn = tf32(sum_sp O_sp / sum_sp l_sp)
// ---------------------------------------------------------------------------
__global__ void combine_kernel(const float* __restrict__ opart,
                               const float* __restrict__ lpart,
                               float* __restrict__ out)
{
    int i = blockIdx.x * blockDim.x + threadIdx.x;   // float4 index
    if (i >= N_TOK * D_MODEL / 4) return;
    int r  = i / (D_MODEL / 4);
    int c4 = (i % (D_MODEL / 4)) * 4;
    int h  = c4 >> 6;
    float l = 0.0f;
    float4 a = make_float4(0.0f, 0.0f, 0.0f, 0.0f);
#pragma unroll
    for (int sp = 0; sp < KV_SPLIT; sp++) {
        l += lpart[(size_t)sp * N_HEADS * N_TOK + (size_t)h * N_TOK + r];
        float4 t = ((const float4*)(opart + (size_t)sp * N_TOK * D_MODEL))[i];
        a.x += t.x; a.y += t.y; a.z += t.z; a.w += t.w;
    }
    float inv = 1.0f / l;
    float4 o;
    o.x = f2tf32f(a.x * inv); o.y = f2tf32f(a.y * inv);
    o.z = f2tf32f(a.z * inv); o.w = f2tf32f(a.w * inv);
    ((float4*)out)[i] = o;
}

// ---------------------------------------------------------------------------
// Launch
// ---------------------------------------------------------------------------
extern "C" void kernel_launch(void* const* d_in, const int* in_sizes, int n_in,
                              void* d_out, int out_size)
{
    const float* Q  = (const float*)d_in[0];
    const float* K  = (const float*)d_in[1];
    const float* V  = (const float*)d_in[2];
    const float* Wq = (const float*)d_in[3];
    const float* bq = (const float*)d_in[4];
    const float* Wk = (const float*)d_in[5];
    const float* bk = (const float*)d_in[6];
    const float* Wv = (const float*)d_in[7];
    const float* bv = (const float*)d_in[8];
    const float* Wo = (const float*)d_in[9];
    const float* bo = (const float*)d_in[10];
    float* out = (float*)d_out;

    float *qb, *kb, *vb, *ab, *xc, *wc, *op, *lp;
    cudaGetSymbolAddress((void**)&qb, g_q);
    cudaGetSymbolAddress((void**)&kb, g_k);
    cudaGetSymbolAddress((void**)&vb, g_v);
    cudaGetSymbolAddress((void**)&ab, g_attn);
    cudaGetSymbolAddress((void**)&xc, g_xc);
    cudaGetSymbolAddress((void**)&wc, g_wc);
    cudaGetSymbolAddress((void**)&op, g_op);
    cudaGetSymbolAddress((void**)&lp, g_lp);

    float* xc0 = xc;
    float* xc1 = xc + (size_t)N_TOK * D_MODEL;
    float* xc2 = xc + 2 * (size_t)N_TOK * D_MODEL;
    float* wc0 = wc;
    float* wc1 = wc + (size_t)D_MODEL * D_MODEL;
    float* wc2 = wc + 2 * (size_t)D_MODEL * D_MODEL;
    float* wc3 = wc + 3 * (size_t)D_MODEL * D_MODEL;

    // Idempotent, capture-safe (not stream ops).
    cudaFuncSetAttribute(attn_tc_kernel,
                         cudaFuncAttributeMaxDynamicSharedMemorySize, ATT_SMEM_BYTES);
    cudaFuncSetAttribute(qkv_gemm_kernel,
                         cudaFuncAttributeMaxDynamicSharedMemorySize, GEMM_SMEM_BYTES);
    cudaFuncSetAttribute(gemm_o_kernel,
                         cudaFuncAttributeMaxDynamicSharedMemorySize, GEMM_SMEM_BYTES);

    // 1) Pre-convert operands to tf32 (RNA), 2 fused launches.
    dim3 cvtIGrid((NX4 + 255) / 256, 3);
    cvt_inputs_kernel<<<cvtIGrid, 256>>>((const float4*)Q, (const float4*)K,
                                         (const float4*)V, (float4*)xc);
    dim3 cvtWGrid((NW4 + 255) / 256, 4);
    cvt_weights_kernel<<<cvtWGrid, 256>>>((const float4*)Wq, (const float4*)Wk,
                                          (const float4*)Wv, (const float4*)Wo,
                                          (float4*)wc);

    // 2) Fused QKV projections (V written transposed).
    dim3 qkvGrid(D_MODEL / GBN, N_TOK / GBM, 3);   // (6, 32, 3)
    qkv_gemm_kernel<<<qkvGrid, 256, GEMM_SMEM_BYTES>>>(
        xc0, xc1, xc2, wc0, wc1, wc2, bq, bk, bv, qb, kb, vb);

    // 3) Split-KV attention.
    dim3 attnGrid(N_TOK / 128, N_HEADS, KV_SPLIT); // (32, 12, 4)
    attn_tc_kernel<<<attnGrid, 256, ATT_SMEM_BYTES>>>(qb, kb, vb, op, lp);

    // 4) Combine partials -> g_attn (tf32 bits).
    combine_kernel<<<(NX4 + 255) / 256, 256>>>(op, lp, ab);

    // 5) Output projection.
    dim3 oGrid(D_MODEL / GBN, N_TOK / GBM);        // (6, 32)
    gemm_o_kernel<<<oGrid, 256, GEMM_SMEM_BYTES>>>(ab, wc3, bo, out);
}

// round 12
// speedup vs baseline: 5.4382x; 1.0427x over previous
#include <cuda_runtime.h>
#include <cstdint>

// Problem constants
#define N_TOK   4096
#define D_MODEL 768
#define N_HEADS 12
#define D_K     64
#define KV_SPLIT 4
#define SPLIT_LEN (N_TOK / KV_SPLIT)   // 1024

// ---------------------------------------------------------------------------
// Scratch buffers (float-typed; several hold tf32-rounded bit patterns)
// ---------------------------------------------------------------------------
__device__ float g_q[N_HEADS * N_TOK * D_K];            // tf32 bits, pre-scaled 0.125
__device__ float g_k[N_HEADS * N_TOK * D_K];            // tf32 bits, [h][tok][dk]
__device__ float g_v[N_HEADS * D_K * N_TOK];            // tf32 bits, TRANSPOSED [h][dk][tok]
__device__ float g_attn[N_TOK * D_MODEL];               // tf32 bits (combine output)
__device__ float g_xc[3][N_TOK * D_MODEL];              // converted inputs Q,K,V
__device__ float g_wc[4][D_MODEL * D_MODEL];            // converted Wq,Wk,Wv,Wo
__device__ float g_op[KV_SPLIT][N_TOK * D_MODEL];       // partial O (unnormalized)
__device__ float g_lp[KV_SPLIT][N_HEADS * N_TOK];       // partial row sums

// ---------------------------------------------------------------------------
// Helpers (baseline sm_80+ PTX only)
// ---------------------------------------------------------------------------
__device__ __forceinline__ uint32_t f2tf32(float f) {
    uint32_t o;
    asm("cvt.rna.tf32.f32 %0, %1;" : "=r"(o) : "f"(f));
    return o;
}
__device__ __forceinline__ float f2tf32f(float f) {
    return __uint_as_float(f2tf32(f));
}
__device__ __forceinline__ uint32_t smem_u32(const void* p) {
    uint32_t a;
    asm("{ .reg .u64 t; cvta.to.shared.u64 t, %1; cvt.u32.u64 %0, t; }" : "=r"(a) : "l"(p));
    return a;
}
#define CP_ASYNC16(dst_u32, src) \
    asm volatile("cp.async.cg.shared.global [%0], [%1], 16;" \
                 :: "r"(dst_u32), "l"(src) : "memory")
#define CP_COMMIT() asm volatile("cp.async.commit_group;" ::: "memory")
#define CP_WAIT1()  asm volatile("cp.async.wait_group 1;" ::: "memory")
#define CP_WAIT0()  asm volatile("cp.async.wait_group 0;" ::: "memory")

__device__ __forceinline__ void ldsm_x4(uint32_t& r0, uint32_t& r1,
                                        uint32_t& r2, uint32_t& r3, uint32_t addr) {
    asm volatile("ldmatrix.sync.aligned.m8n8.x4.shared.b16 {%0,%1,%2,%3}, [%4];"
                 : "=r"(r0), "=r"(r1), "=r"(r2), "=r"(r3) : "r"(addr));
}

// D(16x8) += A(16x8) * B(8x8); A row-major, B col-major; fp32 accum.
__device__ __forceinline__ void mma_tf32(float c[4], const uint32_t a[4],
                                         const uint32_t b[2]) {
    asm volatile(
        "mma.sync.aligned.m16n8k8.row.col.f32.tf32.tf32.f32 "
        "{%0,%1,%2,%3}, {%4,%5,%6,%7}, {%8,%9}, {%0,%1,%2,%3};"
        : "+f"(c[0]), "+f"(c[1]), "+f"(c[2]), "+f"(c[3])
        : "r"(a[0]), "r"(a[1]), "r"(a[2]), "r"(a[3]), "r"(b[0]), "r"(b[1]));
}

// ---------------------------------------------------------------------------
// Fused tf32 pre-conversion: inputs (y=0..2) and weights (y=0..3)
// ---------------------------------------------------------------------------
#define NX4 (N_TOK * D_MODEL / 4)
#define NW4 (D_MODEL * D_MODEL / 4)

__global__ void cvt_inputs_kernel(const float4* __restrict__ a,
                                  const float4* __restrict__ b,
                                  const float4* __restrict__ cc,
                                  float4* __restrict__ dst)
{
    int i = blockIdx.x * blockDim.x + threadIdx.x;
    if (i >= NX4) return;
    const float4* src = (blockIdx.y == 0) ? a : (blockIdx.y == 1) ? b : cc;
    float4 t = src[i];
    t.x = f2tf32f(t.x); t.y = f2tf32f(t.y);
    t.z = f2tf32f(t.z); t.w = f2tf32f(t.w);
    dst[(size_t)blockIdx.y * NX4 + i] = t;
}
__global__ void cvt_weights_kernel(const float4* __restrict__ a,
                                   const float4* __restrict__ b,
                                   const float4* __restrict__ cc,
                                   const float4* __restrict__ d,
                                   float4* __restrict__ dst)
{
    int i = blockIdx.x * blockDim.x + threadIdx.x;
    if (i >= NW4) return;
    const float4* src = (blockIdx.y == 0) ? a : (blockIdx.y == 1) ? b
                      : (blockIdx.y == 2) ? cc : d;
    float4 t = src[i];
    t.x = f2tf32f(t.x); t.y = f2tf32f(t.y);
    t.z = f2tf32f(t.z); t.w = f2tf32f(t.w);
    dst[(size_t)blockIdx.y * NW4 + i] = t;
}

// ---------------------------------------------------------------------------
// GEMM mainloop (shared): block 128x128x32, 8 warps (2x4), warp tile 64x32,
// cp.async double-buffered, operands pre-converted tf32 bits (no cvt in loop).
// ---------------------------------------------------------------------------
#define GBM 128
#define GBN 128
#define GBK 32
#define GST 36
#define GEMM_SMEM_BYTES (2 * 2 * GBM * GST * 4)
#define GEMM_NIT (D_MODEL / GBK)   // 24

#define GEMM_PREFETCH(as_, bs_, Xp_, Wp_, k0_) \
    do { \
        for (int i_ = tid; i_ < 1024; i_ += 256) { \
            int r_ = i_ >> 3, c4_ = (i_ & 7) * 4; \
            CP_ASYNC16((as_) + (r_ * GST + c4_) * 4, (Xp_) + (size_t)r_ * D_MODEL + (k0_) + c4_); \
            CP_ASYNC16((bs_) + (r_ * GST + c4_) * 4, (Wp_) + (size_t)r_ * D_MODEL + (k0_) + c4_); \
        } \
        CP_COMMIT(); \
    } while (0)

#define GEMM_MAINLOOP(Xp_, Wp_) \
    { \
        uint32_t as0 = sbase, bs0 = sbase + GBM * GST * 4; \
        GEMM_PREFETCH(as0, bs0, Xp_, Wp_, 0); \
    } \
    for (int it = 0; it < GEMM_NIT; ++it) { \
        const int cur = it & 1; \
        if (it + 1 < GEMM_NIT) { \
            uint32_t as_ = sbase + (uint32_t)(cur ^ 1) * 2 * GBM * GST * 4; \
            uint32_t bs_ = as_ + GBM * GST * 4; \
            GEMM_PREFETCH(as_, bs_, Xp_, Wp_, (it + 1) * GBK); \
            CP_WAIT1(); \
        } else { \
            CP_WAIT0(); \
        } \
        __syncthreads(); \
        const uint32_t* As = gsh + (size_t)cur * 2 * GBM * GST; \
        const uint32_t* Bs = As + GBM * GST; \
        _Pragma("unroll") \
        for (int s = 0; s < 4; s++) { \
            const int c0 = s * 8; \
            uint32_t a[4][4], b[4][2]; \
            _Pragma("unroll") \
            for (int mt = 0; mt < 4; mt++) { \
                int r = wm * 64 + mt * 16 + g; \
                a[mt][0] = As[r * GST + c0 + c]; \
                a[mt][1] = As[(r + 8) * GST + c0 + c]; \
                a[mt][2] = As[r * GST + c0 + c + 4]; \
                a[mt][3] = As[(r + 8) * GST + c0 + c + 4]; \
            } \
            _Pragma("unroll") \
            for (int nt = 0; nt < 4; nt++) { \
                int n = wn * 32 + nt * 8 + g; \
                b[nt][0] = Bs[n * GST + c0 + c]; \
                b[nt][1] = Bs[n * GST + c0 + c + 4]; \
            } \
            _Pragma("unroll") \
            for (int mt = 0; mt < 4; mt++) \
                _Pragma("unroll") \
                for (int nt = 0; nt < 4; nt++) \
                    mma_tf32(acc[mt][nt], a[mt], b[nt]); \
        } \
        __syncthreads(); \
    }

// ---------------------------------------------------------------------------
// Fused QKV projection. Grid (6, 32, 3). z=0: q (scaled, [h][tok][dk]),
// z=1: k ([h][tok][dk]), z=2: v TRANSPOSED ([h][dk][tok]). tf32-rounded.
// ---------------------------------------------------------------------------
__global__ void __launch_bounds__(256) qkv_gemm_kernel(
    const float* __restrict__ x0, const float* __restrict__ x1, const float* __restrict__ x2,
    const float* __restrict__ w0, const float* __restrict__ w1, const float* __restrict__ w2,
    const float* __restrict__ bq_, const float* __restrict__ bk_, const float* __restrict__ bv_,
    float* __restrict__ o0, float* __restrict__ o1, float* __restrict__ o2)
{
    extern __shared__ uint32_t gsh[];
    const int tid  = threadIdx.x;
    const int wid  = tid >> 5;
    const int lane = tid & 31;
    const int g    = lane >> 2;
    const int c    = lane & 3;
    const int wm   = wid >> 2;
    const int wn   = wid & 3;
    const int m0   = blockIdx.y * GBM;
    const int n0   = blockIdx.x * GBN;
    const int z    = blockIdx.z;

    const float* X    = (z == 0) ? x0 : (z == 1) ? x1 : x2;
    const float* W    = (z == 0) ? w0 : (z == 1) ? w1 : w2;
    const float* bias = (z == 0) ? bq_ : (z == 1) ? bk_ : bv_;
    const float scale = (z == 0) ? 0.125f : 1.0f;

    const uint32_t sbase = smem_u32(gsh);
    const float* Xp = X + (size_t)m0 * D_MODEL;
    const float* Wp = W + (size_t)n0 * D_MODEL;

    float acc[4][4][4];
#pragma unroll
    for (int i = 0; i < 4; i++)
#pragma unroll
        for (int j = 0; j < 4; j++)
#pragma unroll
            for (int f = 0; f < 4; f++) acc[i][j][f] = 0.0f;

    GEMM_MAINLOOP(Xp, Wp)

#pragma unroll
    for (int nt = 0; nt < 4; nt++) {
        int col = n0 + wn * 32 + nt * 8 + 2 * c;
        float b0 = bias[col], b1 = bias[col + 1];
        int h = col >> 6, t = col & 63;
#pragma unroll
        for (int mt = 0; mt < 4; mt++) {
            int row = m0 + wm * 64 + mt * 16 + g;
            float v00 = f2tf32f((acc[mt][nt][0] + b0) * scale);
            float v01 = f2tf32f((acc[mt][nt][1] + b1) * scale);
            float v10 = f2tf32f((acc[mt][nt][2] + b0) * scale);
            float v11 = f2tf32f((acc[mt][nt][3] + b1) * scale);
            if (z == 2) {
                float* vp = o2;  // transposed: [h][dk][tok]
                vp[((size_t)h * D_K + t)     * N_TOK + row]     = v00;
                vp[((size_t)h * D_K + t + 1) * N_TOK + row]     = v01;
                vp[((size_t)h * D_K + t)     * N_TOK + row + 8] = v10;
                vp[((size_t)h * D_K + t + 1) * N_TOK + row + 8] = v11;
            } else {
                float* outp = (z == 0) ? o0 : o1;
                *(float2*)&outp[((size_t)h * N_TOK + row) * D_K + t]     = make_float2(v00, v01);
                *(float2*)&outp[((size_t)h * N_TOK + row + 8) * D_K + t] = make_float2(v10, v11);
            }
        }
    }
}

// ---------------------------------------------------------------------------
// Output projection
// ---------------------------------------------------------------------------
__global__ void __launch_bounds__(256) gemm_o_kernel(
    const float* __restrict__ X, const float* __restrict__ W,
    const float* __restrict__ bias, float* __restrict__ out)
{
    extern __shared__ uint32_t gsh[];
    const int tid  = threadIdx.x;
    const int wid  = tid >> 5;
    const int lane = tid & 31;
    const int g    = lane >> 2;
    const int c    = lane & 3;
    const int wm   = wid >> 2;
    const int wn   = wid & 3;
    const int m0   = blockIdx.y * GBM;
    const int n0   = blockIdx.x * GBN;

    const uint32_t sbase = smem_u32(gsh);
    const float* Xp = X + (size_t)m0 * D_MODEL;
    const float* Wp = W + (size_t)n0 * D_MODEL;

    float acc[4][4][4];
#pragma unroll
    for (int i = 0; i < 4; i++)
#pragma unroll
        for (int j = 0; j < 4; j++)
#pragma unroll
            for (int f = 0; f < 4; f++) acc[i][j][f] = 0.0f;

    GEMM_MAINLOOP(Xp, Wp)

#pragma unroll
    for (int nt = 0; nt < 4; nt++) {
        int col = n0 + wn * 32 + nt * 8 + 2 * c;
        float b0 = bias[col], b1 = bias[col + 1];
#pragma unroll
        for (int mt = 0; mt < 4; mt++) {
            int row = m0 + wm * 64 + mt * 16 + g;
            *(float2*)&out[(size_t)row * D_MODEL + col] =
                make_float2(acc[mt][nt][0] + b0, acc[mt][nt][1] + b1);
            *(float2*)&out[(size_t)(row + 8) * D_MODEL + col] =
                make_float2(acc[mt][nt][2] + b0, acc[mt][nt][3] + b1);
        }
    }
}

// ---------------------------------------------------------------------------
// Flash attention, split-KV, ldmatrix loads, 2 m-tiles per warp (B-frag reuse).
// Grid (32, 12, KV_SPLIT), 128 threads (4 warps x 32 q-rows). kv tiles of 64.
// smem: Qp[128*68] (Q then P), Ks 2x[64*68] ([kv][dk]), Vt 2x[64*68] ([dk][kv]).
// ---------------------------------------------------------------------------
#define AST 68
#define VST2 68
#define ATT_QW   (128 * AST)
#define ATT_KW   (64 * AST)
#define ATT_VW   (64 * VST2)
#define ATT_SMEM_BYTES ((ATT_QW + 2 * ATT_KW + 2 * ATT_VW) * 4)
#define ATT_THREADS 128

__global__ void __launch_bounds__(ATT_THREADS, 2) attn_tc_kernel(
    const float* __restrict__ q, const float* __restrict__ k,
    const float* __restrict__ v, float* __restrict__ opart,
    float* __restrict__ lpart)
{
    extern __shared__ uint32_t sh[];
    uint32_t* Qp  = sh;
    uint32_t* Ksb[2] = { sh + ATT_QW, sh + ATT_QW + ATT_KW };
    uint32_t* Vsb[2] = { sh + ATT_QW + 2 * ATT_KW, sh + ATT_QW + 2 * ATT_KW + ATT_VW };

    const int tid  = threadIdx.x;
    const int wid  = tid >> 5;
    const int lane = tid & 31;
    const int g    = lane >> 2;
    const int c    = lane & 3;
    const int wr   = wid * 32;         // this warp's 32-row block
    const int h    = blockIdx.y;
    const int q0   = blockIdx.x * 128;
    const int sp   = blockIdx.z;

    float* op = opart + (size_t)sp * N_TOK * D_MODEL;
    float* lp = lpart + (size_t)sp * N_HEADS * N_TOK;

    const float* kh = k + ((size_t)h * N_TOK + sp * SPLIT_LEN) * D_K;   // [tok][dk]
    const float* vh = v + (size_t)h * D_K * N_TOK + sp * SPLIT_LEN;     // [dk][tok]

    // ldmatrix per-lane address components (bytes)
    const int m_ = lane >> 3, r_ = lane & 7;
    const uint32_t QpA = smem_u32(Qp);
    const uint32_t KsA0 = smem_u32(Ksb[0]), KsA1 = smem_u32(Ksb[1]);
    const uint32_t VsA0 = smem_u32(Vsb[0]), VsA1 = smem_u32(Vsb[1]);
    // K B-frag: matrix m -> kw = 4j+m, row = nt*8 + r
    const uint32_t kOff = (uint32_t)(r_ * AST + 4 * m_) * 4;
    // P A-frag: matrix m -> row = base + (m&1)*8 + r, wcol = s*8 + (m>>1)*4
    const uint32_t pOff = (uint32_t)(((m_ & 1) * 8 + r_) * AST + (m_ >> 1) * 4) * 4;
    // V B-frag: matrix m -> row dk = (2j + (m>>1))*8 + r, wcol = s*8 + (m&1)*4
    const uint32_t vOff = (uint32_t)(((m_ >> 1) * 8 + r_) * VST2 + 4 * (m_ & 1)) * 4;

    // Prefetch kv tile 0.
    {
        uint32_t ks = KsA0, vs = VsA0;
#pragma unroll
        for (int i = tid; i < 1024; i += ATT_THREADS) {
            int r = i >> 4, c4 = (i & 15) * 4;
            CP_ASYNC16(ks + (r * AST + c4) * 4, kh + (size_t)r * D_K + c4);
            CP_ASYNC16(vs + (r * VST2 + c4) * 4, vh + (size_t)r * N_TOK + c4);
        }
        CP_COMMIT();
    }

    // Q tile: already scaled + tf32 bits -> plain copy.
    const float* qh = q + ((size_t)h * N_TOK + q0) * D_K;
#pragma unroll
    for (int i = tid; i < 2048; i += ATT_THREADS) {
        int r = i >> 4, c4 = (i & 15) * 4;
        uint4 t = *(const uint4*)(qh + (size_t)r * D_K + c4);
        *(uint4*)&Qp[r * AST + c4] = t;
    }
    __syncthreads();

    // Persistent Q fragments: 2 m-tiles x 8 k-steps.
    uint32_t qa[2][8][4];
#pragma unroll
    for (int mt = 0; mt < 2; mt++) {
        int rb = wr + mt * 16;
#pragma unroll
        for (int s = 0; s < 8; s++) {
            int c0 = s * 8;
            qa[mt][s][0] = Qp[(rb + g) * AST + c0 + c];
            qa[mt][s][1] = Qp[(rb + g + 8) * AST + c0 + c];
            qa[mt][s][2] = Qp[(rb + g) * AST + c0 + c + 4];
            qa[mt][s][3] = Qp[(rb + g + 8) * AST + c0 + c + 4];
        }
    }
    __syncthreads();  // Q fully read before Qp is reused as P

    float o[2][8][4];
#pragma unroll
    for (int mt = 0; mt < 2; mt++)
#pragma unroll
        for (int nt = 0; nt < 8; nt++)
#pragma unroll
            for (int f = 0; f < 4; f++) o[mt][nt][f] = 0.0f;
    float ls[4] = {0.0f, 0.0f, 0.0f, 0.0f};   // [mt*2 + (0:row g,1:row g+8)]

    const int NIT = SPLIT_LEN / 64;  // 16
    for (int it = 0; it < NIT; ++it) {
        const int cur = it & 1;
        if (it + 1 < NIT) {
            const int kt = (it + 1) * 64;
            uint32_t ks = cur ? KsA0 : KsA1;
            uint32_t vs = cur ? VsA0 : VsA1;
#pragma unroll
            for (int i = tid; i < 1024; i += ATT_THREADS) {
                int r = i >> 4, c4 = (i & 15) * 4;
                CP_ASYNC16(ks + (r * AST + c4) * 4, kh + (size_t)(kt + r) * D_K + c4);
                CP_ASYNC16(vs + (r * VST2 + c4) * 4, vh + (size_t)r * N_TOK + kt + c4);
            }
            CP_COMMIT();
            CP_WAIT1();
        } else {
            CP_WAIT0();
        }
        __syncthreads();

        const uint32_t KsA = cur ? KsA1 : KsA0;
        const uint32_t VsA = cur ? VsA1 : VsA0;

        // S = Q.K^T; each K B-frag reused by both m-tiles; exp; P -> Qp.
#pragma unroll
        for (int nt = 0; nt < 8; nt++) {
            uint32_t bb[8][2];
            const uint32_t kb = KsA + kOff + (uint32_t)nt * (8 * AST * 4);
#pragma unroll
            for (int j = 0; j < 4; j++)
                ldsm_x4(bb[2 * j][0], bb[2 * j][1], bb[2 * j + 1][0], bb[2 * j + 1][1],
                        kb + (uint32_t)j * 64);
#pragma unroll
            for (int mt = 0; mt < 2; mt++) {
                float sfr[4] = {0.0f, 0.0f, 0.0f, 0.0f};
#pragma unroll
                for (int s = 0; s < 8; s++)
                    mma_tf32(sfr, qa[mt][s], bb[s]);
                float p0 = __expf(sfr[0]), p1 = __expf(sfr[1]);
                float p2 = __expf(sfr[2]), p3 = __expf(sfr[3]);
                ls[mt * 2]     += p0 + p1;
                ls[mt * 2 + 1] += p2 + p3;
                int rb = wr + mt * 16;
                int col = nt * 8 + 2 * c;
                *(uint2*)&Qp[(rb + g) * AST + col]     = make_uint2(f2tf32(p0), f2tf32(p1));
                *(uint2*)&Qp[(rb + g + 8) * AST + col] = make_uint2(f2tf32(p2), f2tf32(p3));
            }
        }
        __syncwarp();  // P rows are warp-private

        // O += P.V  (each V B-frag reused by both m-tiles)
#pragma unroll
        for (int s = 0; s < 8; s++) {
            uint32_t pa[2][4];
#pragma unroll
            for (int mt = 0; mt < 2; mt++)
                ldsm_x4(pa[mt][0], pa[mt][1], pa[mt][2], pa[mt][3],
                        QpA + pOff + (uint32_t)((wr + mt * 16) * AST) * 4 + (uint32_t)s * 32);
            const uint32_t vb = VsA + vOff + (uint32_t)s * 32;
#pragma unroll
            for (int j = 0; j < 4; j++) {
                uint32_t b0, b1, b2, b3;
                ldsm_x4(b0, b1, b2, b3, vb + (uint32_t)j * (16 * VST2 * 4));
                uint32_t bA[2] = {b0, b1}, bB[2] = {b2, b3};
#pragma unroll
                for (int mt = 0; mt < 2; mt++) {
                    mma_tf32(o[mt][2 * j], pa[mt], bA);
                    mma_tf32(o[mt][2 * j + 1], pa[mt], bB);
                }
            }
        }
        __syncthreads();  // all reads of buf[cur] done before next prefetch
    }

    // Row sums across the 4-lane quad; write l and O for both m-tiles.
#pragma unroll
    for (int i = 0; i < 4; i++) {
        ls[i] += __shfl_xor_sync(0xffffffffu, ls[i], 1);
        ls[i] += __shfl_xor_sync(0xffffffffu, ls[i], 2);
    }
    if (c == 0) {
#pragma unroll
        for (int mt = 0; mt < 2; mt++) {
            lp[(size_t)h * N_TOK + q0 + wr + mt * 16 + g]     = ls[mt * 2];
            lp[(size_t)h * N_TOK + q0 + wr + mt * 16 + g + 8] = ls[mt * 2 + 1];
        }
    }

#pragma unroll
    for (int mt = 0; mt < 2; mt++) {
        int rb = q0 + wr + mt * 16;
#pragma unroll
        for (int nt = 0; nt < 8; nt++) {
            int col = h * D_K + nt * 8 + 2 * c;
            *(float2*)&op[(size_t)(rb + g) * D_MODEL + col] =
                make_float2(o[mt][nt][0], o[mt][nt][1]);
            *(float2*)&op[(size_t)(rb + g + 8) * D_MODEL + col] =
                make_float2(o[mt][nt][2], o[mt][nt][3]);
        }
    }
}

// ---------------------------------------------------------------------------
// Combine: attn = tf32(sum_sp O_sp / sum_sp l_sp)
// ---------------------------------------------------------------------------
__global__ void combine_kernel(const float* __restrict__ opart,
                               const float* __restrict__ lpart,
                               float* __restrict__ out)
{
    int i = blockIdx.x * blockDim.x + threadIdx.x;   // float4 index
    if (i >= N_TOK * D_MODEL / 4) return;
    int r  = i / (D_MODEL / 4);
    int c4 = (i % (D_MODEL / 4)) * 4;
    int h  = c4 >> 6;
    float l = 0.0f;
    float4 a = make_float4(0.0f, 0.0f, 0.0f, 0.0f);
#pragma unroll
    for (int sp = 0; sp < KV_SPLIT; sp++) {
        l += lpart[(size_t)sp * N_HEADS * N_TOK + (size_t)h * N_TOK + r];
        float4 t = ((const float4*)(opart + (size_t)sp * N_TOK * D_MODEL))[i];
        a.x += t.x; a.y += t.y; a.z += t.z; a.w += t.w;
    }
    float inv = 1.0f / l;
    float4 o;
    o.x = f2tf32f(a.x * inv); o.y = f2tf32f(a.y * inv);
    o.z = f2tf32f(a.z * inv); o.w = f2tf32f(a.w * inv);
    ((float4*)out)[i] = o;
}

// ---------------------------------------------------------------------------
// Launch
// ---------------------------------------------------------------------------
extern "C" void kernel_launch(void* const* d_in, const int* in_sizes, int n_in,
                              void* d_out, int out_size)
{
    const float* Q  = (const float*)d_in[0];
    const float* K  = (const float*)d_in[1];
    const float* V  = (const float*)d_in[2];
    const float* Wq = (const float*)d_in[3];
    const float* bq = (const float*)d_in[4];
    const float* Wk = (const float*)d_in[5];
    const float* bk = (const float*)d_in[6];
    const float* Wv = (const float*)d_in[7];
    const float* bv = (const float*)d_in[8];
    const float* Wo = (const float*)d_in[9];
    const float* bo = (const float*)d_in[10];
    float* out = (float*)d_out;

    float *qb, *kb, *vb, *ab, *xc, *wc, *op, *lp;
    cudaGetSymbolAddress((void**)&qb, g_q);
    cudaGetSymbolAddress((void**)&kb, g_k);
    cudaGetSymbolAddress((void**)&vb, g_v);
    cudaGetSymbolAddress((void**)&ab, g_attn);
    cudaGetSymbolAddress((void**)&xc, g_xc);
    cudaGetSymbolAddress((void**)&wc, g_wc);
    cudaGetSymbolAddress((void**)&op, g_op);
    cudaGetSymbolAddress((void**)&lp, g_lp);

    float* xc0 = xc;
    float* xc1 = xc + (size_t)N_TOK * D_MODEL;
    float* xc2 = xc + 2 * (size_t)N_TOK * D_MODEL;
    float* wc0 = wc;
    float* wc1 = wc + (size_t)D_MODEL * D_MODEL;
    float* wc2 = wc + 2 * (size_t)D_MODEL * D_MODEL;
    float* wc3 = wc + 3 * (size_t)D_MODEL * D_MODEL;

    // Idempotent, capture-safe (not stream ops).
    cudaFuncSetAttribute(attn_tc_kernel,
                         cudaFuncAttributeMaxDynamicSharedMemorySize, ATT_SMEM_BYTES);
    cudaFuncSetAttribute(qkv_gemm_kernel,
                         cudaFuncAttributeMaxDynamicSharedMemorySize, GEMM_SMEM_BYTES);
    cudaFuncSetAttribute(gemm_o_kernel,
                         cudaFuncAttributeMaxDynamicSharedMemorySize, GEMM_SMEM_BYTES);

    // 1) Pre-convert operands to tf32 (RNA), 2 fused launches.
    dim3 cvtIGrid((NX4 + 255) / 256, 3);
    cvt_inputs_kernel<<<cvtIGrid, 256>>>((const float4*)Q, (const float4*)K,
                                         (const float4*)V, (float4*)xc);
    dim3 cvtWGrid((NW4 + 255) / 256, 4);
    cvt_weights_kernel<<<cvtWGrid, 256>>>((const float4*)Wq, (const float4*)Wk,
                                          (const float4*)Wv, (const float4*)Wo,
                                          (float4*)wc);

    // 2) Fused QKV projections (V written transposed).
    dim3 qkvGrid(D_MODEL / GBN, N_TOK / GBM, 3);   // (6, 32, 3)
    qkv_gemm_kernel<<<qkvGrid, 256, GEMM_SMEM_BYTES>>>(
        xc0, xc1, xc2, wc0, wc1, wc2, bq, bk, bv, qb, kb, vb);

    // 3) Split-KV attention (128 threads, 4 warps x 32 rows).
    dim3 attnGrid(N_TOK / 128, N_HEADS, KV_SPLIT); // (32, 12, 4)
    attn_tc_kernel<<<attnGrid, ATT_THREADS, ATT_SMEM_BYTES>>>(qb, kb, vb, op, lp);

    // 4) Combine partials -> g_attn (tf32 bits).
    combine_kernel<<<(NX4 + 255) / 256, 256>>>(op, lp, ab);

    // 5) Output projection.
    dim3 oGrid(D_MODEL / GBN, N_TOK / GBM);        // (6, 32)
    gemm_o_kernel<<<oGrid, 256, GEMM_SMEM_BYTES>>>(ab, wc3, bo, out);
}